// round 8
// baseline (speedup 1.0000x reference)
#include <cuda_runtime.h>
#include <cuda_bf16.h>
#include <math.h>

#define BATCH   1024
#define IN_DIM  768
#define HID     512
#define OUT_DIM 256
#define KE1     (IN_DIM * 3)   // 2304 ext
#define KE2     (HID * 3)      // 1536 ext

// ---- scratch (__device__ globals; allocation-free rule) ----
__device__ float          g_A[BATCH * HID];
__device__ float          g_T[BATCH * HID];
__device__ unsigned short g_Xc1[BATCH * KE1];     // combin split [h,h,l]
__device__ unsigned short g_Xc2[BATCH * KE2];     // s_emb  split [h,h,l]
__device__ unsigned short g_Wc1[HID * KE1];       // W2 split [h,l,h]
__device__ unsigned short g_Wc2[HID * KE2];       // W1 split [h,l,h]
__device__ unsigned short g_Wc3[OUT_DIM * KE2];   // W3 split [h,l,h]
__device__ unsigned short g_Mc[BATCH * KE2];      // attn out split [h,h,l]

__device__ __forceinline__ float ex2f_(float x) {
    float y; asm("ex2.approx.f32 %0, %1;" : "=f"(y) : "f"(x)); return y;
}
__device__ __forceinline__ float rcpf_(float x) {
    float y; asm("rcp.approx.f32 %0, %1;" : "=f"(y) : "f"(x)); return y;
}
__device__ __forceinline__ void split2(float v, unsigned &h, unsigned &l) {
    __nv_bfloat16 hb = __float2bfloat16(v);
    float lo = v - __bfloat162float(hb);
    h = (unsigned)__bfloat16_as_ushort(hb);
    l = (unsigned)__bfloat16_as_ushort(__float2bfloat16(lo));
}
__device__ __forceinline__ void ldsm4(unsigned addr, unsigned &r0, unsigned &r1,
                                      unsigned &r2, unsigned &r3) {
    asm volatile("ldmatrix.sync.aligned.m8n8.x4.shared.b16 {%0,%1,%2,%3}, [%4];"
                 : "=r"(r0), "=r"(r1), "=r"(r2), "=r"(r3) : "r"(addr));
}
__device__ __forceinline__ void mma_bf16(float c[4], unsigned a0, unsigned a1,
                                         unsigned a2, unsigned a3,
                                         unsigned b0, unsigned b1) {
    asm volatile(
        "mma.sync.aligned.m16n8k16.row.col.f32.bf16.bf16.f32 "
        "{%0,%1,%2,%3}, {%4,%5,%6,%7}, {%8,%9}, {%0,%1,%2,%3};\n"
        : "+f"(c[0]), "+f"(c[1]), "+f"(c[2]), "+f"(c[3])
        : "r"(a0), "r"(a1), "r"(a2), "r"(a3), "r"(b0), "r"(b1));
}
__device__ __forceinline__ void cpasync16(unsigned s, const void* g) {
    asm volatile("cp.async.cg.shared.global [%0], [%1], 16;" :: "r"(s), "l"(g));
}

// ---------------------------------------------------------------------------
// One-pass fp32 -> 3-split-bf16 interleave conversion for 5 matrices.
// X layout per elem: [h,h,l]; W layout: [h,l,h] (dot = xh*wh + xh*wl + xl*wh)
// ---------------------------------------------------------------------------
struct ConvDesc { const float* in; unsigned short* out; int pairs; int isW; };

__global__ __launch_bounds__(256) void convert5(
    ConvDesc d0, ConvDesc d1, ConvDesc d2, ConvDesc d3, ConvDesc d4)
{
    ConvDesc d;
    switch (blockIdx.y) {
        case 0: d = d0; break; case 1: d = d1; break; case 2: d = d2; break;
        case 3: d = d3; break; default: d = d4; break;
    }
    int p = blockIdx.x * 256 + threadIdx.x;
    if (p >= d.pairs) return;
    float2 v = ((const float2*)d.in)[p];
    unsigned h0, l0, h1, l1;
    split2(v.x, h0, l0); split2(v.y, h1, l1);
    unsigned* o = (unsigned*)d.out + 3 * (size_t)p;
    if (d.isW) {
        o[0] = h0 | (l0 << 16); o[1] = h0 | (h1 << 16); o[2] = l1 | (h1 << 16);
    } else {
        o[0] = h0 | (h0 << 16); o[1] = l0 | (h1 << 16); o[2] = h1 | (l1 << 16);
    }
}

// ---------------------------------------------------------------------------
// bf16 TN GEMM on pre-split operands:
//   Y[M,N] = (A[M,Kx]_ext @ B[N,Kx]_ext^T + bias) * osc
// CTA 128x64, BKext=64, 256 thr (8 warps, 4m x 2n, warp tile 32x32),
// cp.async double-buffer, XOR-swizzled smem, ldmatrix + mma.m16n8k16.
// z selects one of two fused problems.
// ---------------------------------------------------------------------------
#define GBM 128
#define GBN 64
#define GBK 64

__global__ __launch_bounds__(256) void gemm_mma(
    const unsigned short* A0, const unsigned short* B0, const float* bias0,
    float* Y0, int Kx0, float osc0,
    const unsigned short* A1, const unsigned short* B1, const float* bias1,
    float* Y1, int Kx1, float osc1, int N)
{
    __shared__ __align__(16) unsigned char sm[2 * 16384 + 2 * 8192];

    const unsigned short* A; const unsigned short* B;
    const float* bias; float* Y; int Kx; float osc;
    if (blockIdx.z == 0) { A = A0; B = B0; bias = bias0; Y = Y0; Kx = Kx0; osc = osc0; }
    else                 { A = A1; B = B1; bias = bias1; Y = Y1; Kx = Kx1; osc = osc1; }

    const int tid  = threadIdx.x;
    const int lane = tid & 31;
    const int wid  = tid >> 5;
    const int bm   = blockIdx.y * GBM;
    const int bn   = blockIdx.x * GBN;
    const int wm   = (wid & 3) * 32;
    const int wn   = (wid >> 2) * 32;

    const unsigned smBase = (unsigned)__cvta_generic_to_shared(sm);

    float acc[2][4][4];
#pragma unroll
    for (int i = 0; i < 2; i++)
#pragma unroll
        for (int j = 0; j < 4; j++)
#pragma unroll
            for (int r = 0; r < 4; r++) acc[i][j][r] = 0.f;

    // loader mappings (16B granules), smem col-group XOR-swizzled by row&7
    const int la_r = (tid * 4) >> 3;          // A rows: thread covers 4 granules,
    const int la_g = (tid * 4) & 7;           // g..g+3 within one/two rows
    const int lb_r = (tid * 2) >> 3;
    const int lb_g = (tid * 2) & 7;

    const int NT = Kx / GBK;

    // ldmatrix per-lane address components
    const int arow = wm + (lane & 15);                       // + mf*16
    const int akg  = lane >> 4;
    const int brow = wn + (lane & 7) + ((lane >> 4) << 3);   // + nset*16
    const int bkg  = (lane >> 3) & 1;
    const unsigned aOff0 = (unsigned)(arow * 128);
    const unsigned aOff1 = (unsigned)((arow + 16) * 128);
    const unsigned bOff0 = (unsigned)(brow * 128);
    const unsigned bOff1 = (unsigned)((brow + 16) * 128);
    const int ax = arow & 7;     // (+16 preserves low bits)
    const int bx = brow & 7;

#define LOAD_STAGE(KT, S)                                                      \
    {                                                                          \
        _Pragma("unroll")                                                      \
        for (int i = 0; i < 4; i++) {                                          \
            int idx = tid * 4 + i; int r = idx >> 3, g = idx & 7;              \
            unsigned sa = smBase + (S) * 16384 + r * 128 + ((g ^ (r & 7)) << 4);\
            cpasync16(sa, A + (size_t)(bm + r) * Kx + (KT) * GBK + g * 8);     \
        }                                                                      \
        _Pragma("unroll")                                                      \
        for (int i = 0; i < 2; i++) {                                          \
            int idx = tid * 2 + i; int r = idx >> 3, g = idx & 7;              \
            unsigned sa = smBase + 32768 + (S) * 8192 + r * 128 + ((g ^ (r & 7)) << 4);\
            cpasync16(sa, B + (size_t)(bn + r) * Kx + (KT) * GBK + g * 8);     \
        }                                                                      \
        asm volatile("cp.async.commit_group;");                                \
    }

    LOAD_STAGE(0, 0);

    for (int kt = 0; kt < NT; kt++) {
        const int cur = kt & 1;
        if (kt + 1 < NT) {
            LOAD_STAGE(kt + 1, cur ^ 1);
            asm volatile("cp.async.wait_group 1;");
        } else {
            asm volatile("cp.async.wait_group 0;");
        }
        __syncthreads();

        const unsigned sA = smBase + cur * 16384;
        const unsigned sB = smBase + 32768 + cur * 8192;
#pragma unroll
        for (int ks = 0; ks < 4; ks++) {
            unsigned ga = (unsigned)(((2 * ks + akg) ^ ax) << 4);
            unsigned gb = (unsigned)(((2 * ks + bkg) ^ bx) << 4);
            unsigned a0[4], a1[4], bb0[4], bb1[4];
            ldsm4(sA + aOff0 + ga, a0[0], a0[1], a0[2], a0[3]);
            ldsm4(sA + aOff1 + ga, a1[0], a1[1], a1[2], a1[3]);
            ldsm4(sB + bOff0 + gb, bb0[0], bb0[1], bb0[2], bb0[3]);
            ldsm4(sB + bOff1 + gb, bb1[0], bb1[1], bb1[2], bb1[3]);
            mma_bf16(acc[0][0], a0[0], a0[1], a0[2], a0[3], bb0[0], bb0[1]);
            mma_bf16(acc[0][1], a0[0], a0[1], a0[2], a0[3], bb0[2], bb0[3]);
            mma_bf16(acc[0][2], a0[0], a0[1], a0[2], a0[3], bb1[0], bb1[1]);
            mma_bf16(acc[0][3], a0[0], a0[1], a0[2], a0[3], bb1[2], bb1[3]);
            mma_bf16(acc[1][0], a1[0], a1[1], a1[2], a1[3], bb0[0], bb0[1]);
            mma_bf16(acc[1][1], a1[0], a1[1], a1[2], a1[3], bb0[2], bb0[3]);
            mma_bf16(acc[1][2], a1[0], a1[1], a1[2], a1[3], bb1[0], bb1[1]);
            mma_bf16(acc[1][3], a1[0], a1[1], a1[2], a1[3], bb1[2], bb1[3]);
        }
        __syncthreads();
    }
#undef LOAD_STAGE

    const int g  = lane >> 2;
    const int c2 = (lane & 3) * 2;
#pragma unroll
    for (int mf = 0; mf < 2; mf++)
#pragma unroll
        for (int nf = 0; nf < 4; nf++) {
            int col = bn + wn + nf * 8 + c2;
            float2 bv = *(const float2*)(bias + col);
            int r0 = bm + wm + mf * 16 + g;
            float2 o0, o1;
            o0.x = (acc[mf][nf][0] + bv.x) * osc;
            o0.y = (acc[mf][nf][1] + bv.y) * osc;
            o1.x = (acc[mf][nf][2] + bv.x) * osc;
            o1.y = (acc[mf][nf][3] + bv.y) * osc;
            *(float2*)(Y + (size_t)r0 * N + col)       = o0;
            *(float2*)(Y + (size_t)(r0 + 8) * N + col) = o1;
        }
}

// ---------------------------------------------------------------------------
// Chebyshev attention (unchanged math); output written directly as the
// 3-split [h,h,l] bf16 row for GEMM3's A operand.
// ---------------------------------------------------------------------------
#define NNODE 16
__global__ __launch_bounds__(512) void attn_cheb(
    const float* __restrict__ A, const float* __restrict__ T,
    const float* __restrict__ S, unsigned short* __restrict__ Mc)
{
    __shared__ float tex[HID], ssh[HID];
    __shared__ float rmin[16], rmax[16];
    __shared__ float nodeN[NNODE], nodeD[NNODE];
    __shared__ float cN[NNODE], cD[NNODE];
    __shared__ float mh[2];

    const int b = blockIdx.x;
    const int tid = threadIdx.x;
    const int lane = tid & 31;
    const int w = tid >> 5;

    tex[tid] = T[(size_t)b * HID + tid] * 1.44269504088896f;
    ssh[tid] = S[(size_t)b * HID + tid];
    float a = A[(size_t)b * HID + tid];

    float mn = a, mx = a;
#pragma unroll
    for (int o = 16; o; o >>= 1) {
        mn = fminf(mn, __shfl_xor_sync(0xffffffffu, mn, o));
        mx = fmaxf(mx, __shfl_xor_sync(0xffffffffu, mx, o));
    }
    if (lane == 0) { rmin[w] = mn; rmax[w] = mx; }
    __syncthreads();
    if (tid == 0) {
        float mn2 = rmin[0], mx2 = rmax[0];
#pragma unroll
        for (int i = 1; i < 16; i++) { mn2 = fminf(mn2, rmin[i]); mx2 = fmaxf(mx2, rmax[i]); }
        mh[0] = 0.5f * (mn2 + mx2);
        mh[1] = 0.5f * (mx2 - mn2) + 1e-12f;
    }
    __syncthreads();
    const float m = mh[0], h = mh[1];

    const float xk = fmaf(h, cospif((w + 0.5f) * (1.0f / NNODE)), m);
    float aN = 0.f, aD = 0.f;
#pragma unroll 8
    for (int j = lane; j < HID; j += 32) {
        float e = ex2f_(xk * tex[j]);
        aD += e;
        aN = fmaf(e, ssh[j], aN);
    }
#pragma unroll
    for (int o = 16; o; o >>= 1) {
        aN += __shfl_xor_sync(0xffffffffu, aN, o);
        aD += __shfl_xor_sync(0xffffffffu, aD, o);
    }
    if (lane == 0) { nodeN[w] = aN; nodeD[w] = aD; }
    __syncthreads();

    if (tid < 32) {
        const int n = tid & 15;
        const float* V = (tid < 16) ? nodeN : nodeD;
        float c = 0.f;
#pragma unroll
        for (int k = 0; k < NNODE; k++)
            c += V[k] * cospif((float)(n * (2 * k + 1)) * (1.0f / 32.0f));
        c *= (n == 0) ? (1.0f / NNODE) : (2.0f / NNODE);
        ((tid < 16) ? cN : cD)[n] = c;
    }
    __syncthreads();

    const float u = (a - m) * rcpf_(h);
    const float u2 = u + u;
    float bN1 = 0.f, bN2 = 0.f, bD1 = 0.f, bD2 = 0.f;
#pragma unroll
    for (int n = NNODE - 1; n >= 1; --n) {
        float tN = fmaf(u2, bN1, cN[n] - bN2);
        float tD = fmaf(u2, bD1, cD[n] - bD2);
        bN2 = bN1; bN1 = tN;
        bD2 = bD1; bD1 = tD;
    }
    float fN = fmaf(u, bN1, cN[0] - bN2);
    float fD = fmaf(u, bD1, cD[0] - bD2);
    float v = fN * rcpf_(fD);
    v = v > 0.f ? v : 0.f;

    unsigned hh, ll;
    split2(v, hh, ll);
    unsigned short* o = Mc + (size_t)b * KE2 + 3 * tid;
    o[0] = (unsigned short)hh; o[1] = (unsigned short)hh; o[2] = (unsigned short)ll;
}

extern "C" void kernel_launch(void* const* d_in, const int* in_sizes, int n_in,
                              void* d_out, int out_size)
{
    const float* combin = (const float*)d_in[0];
    const float* s_emb  = (const float*)d_in[1];
    const float* W1     = (const float*)d_in[2];
    const float* b1     = (const float*)d_in[3];
    const float* W2     = (const float*)d_in[4];
    const float* b2     = (const float*)d_in[5];
    const float* W3     = (const float*)d_in[6];
    const float* b3     = (const float*)d_in[7];
    float* out = (float*)d_out;

    float *A, *T;
    unsigned short *Xc1, *Xc2, *Wc1, *Wc2, *Wc3, *Mc;
    cudaGetSymbolAddress((void**)&A,   g_A);
    cudaGetSymbolAddress((void**)&T,   g_T);
    cudaGetSymbolAddress((void**)&Xc1, g_Xc1);
    cudaGetSymbolAddress((void**)&Xc2, g_Xc2);
    cudaGetSymbolAddress((void**)&Wc1, g_Wc1);
    cudaGetSymbolAddress((void**)&Wc2, g_Wc2);
    cudaGetSymbolAddress((void**)&Wc3, g_Wc3);
    cudaGetSymbolAddress((void**)&Mc,  g_Mc);

    const float sigma = 0.044194173824159216f;  // 1/sqrt(512)

    ConvDesc d0 = { combin, Xc1, BATCH * IN_DIM / 2, 0 };
    ConvDesc d1 = { s_emb,  Xc2, BATCH * HID / 2,    0 };
    ConvDesc d2 = { W2,     Wc1, HID * IN_DIM / 2,   1 };
    ConvDesc d3 = { W1,     Wc2, HID * HID / 2,      1 };
    ConvDesc d4 = { W3,     Wc3, OUT_DIM * HID / 2,  1 };
    convert5<<<dim3(BATCH * IN_DIM / 2 / 256, 5), 256>>>(d0, d1, d2, d3, d4);

    gemm_mma<<<dim3(HID / GBN, BATCH / GBM, 2), 256>>>(
        Xc1, Wc1, b2, A, KE1, sigma,
        Xc2, Wc2, b1, T, KE2, 1.0f, HID);

    attn_cheb<<<BATCH, 512>>>(A, T, s_emb, Mc);

    gemm_mma<<<dim3(OUT_DIM / GBN, BATCH / GBM, 1), 256>>>(
        Mc, Wc3, b3, out, KE2, 1.0f,
        Mc, Wc3, b3, out, KE2, 1.0f, OUT_DIM);
}

// round 9
// speedup vs baseline: 1.3048x; 1.3048x over previous
#include <cuda_runtime.h>
#include <cuda_bf16.h>
#include <math.h>

#define BATCH   1024
#define IN_DIM  768
#define HID     512
#define OUT_DIM 256
#define KE1     (IN_DIM * 3)   // 2304 ext
#define KE2     (HID * 3)      // 1536 ext

// ---- scratch (__device__ globals; allocation-free rule) ----
__device__ float          g_A[BATCH * HID];
__device__ float          g_T[BATCH * HID];
__device__ unsigned short g_Xc1[BATCH * KE1];     // combin split [h,h,l]
__device__ unsigned short g_Xc2[BATCH * KE2];     // s_emb  split [h,h,l]
__device__ unsigned short g_Wc1[HID * KE1];       // W2 split [h,l,h]
__device__ unsigned short g_Wc2[HID * KE2];       // W1 split [h,l,h]
__device__ unsigned short g_Wc3[OUT_DIM * KE2];   // W3 split [h,l,h]
__device__ unsigned short g_Mc[BATCH * KE2];      // attn out split [h,h,l]

__device__ __forceinline__ float ex2f_(float x) {
    float y; asm("ex2.approx.f32 %0, %1;" : "=f"(y) : "f"(x)); return y;
}
__device__ __forceinline__ float rcpf_(float x) {
    float y; asm("rcp.approx.f32 %0, %1;" : "=f"(y) : "f"(x)); return y;
}
__device__ __forceinline__ void split2(float v, unsigned &h, unsigned &l) {
    __nv_bfloat16 hb = __float2bfloat16(v);
    float lo = v - __bfloat162float(hb);
    h = (unsigned)__bfloat16_as_ushort(hb);
    l = (unsigned)__bfloat16_as_ushort(__float2bfloat16(lo));
}
__device__ __forceinline__ void ldsm4(unsigned addr, unsigned &r0, unsigned &r1,
                                      unsigned &r2, unsigned &r3) {
    asm volatile("ldmatrix.sync.aligned.m8n8.x4.shared.b16 {%0,%1,%2,%3}, [%4];"
                 : "=r"(r0), "=r"(r1), "=r"(r2), "=r"(r3) : "r"(addr));
}
__device__ __forceinline__ void mma_bf16(float c[4], unsigned a0, unsigned a1,
                                         unsigned a2, unsigned a3,
                                         unsigned b0, unsigned b1) {
    asm volatile(
        "mma.sync.aligned.m16n8k16.row.col.f32.bf16.bf16.f32 "
        "{%0,%1,%2,%3}, {%4,%5,%6,%7}, {%8,%9}, {%0,%1,%2,%3};\n"
        : "+f"(c[0]), "+f"(c[1]), "+f"(c[2]), "+f"(c[3])
        : "r"(a0), "r"(a1), "r"(a2), "r"(a3), "r"(b0), "r"(b1));
}
__device__ __forceinline__ void cpasync16(unsigned s, const void* g) {
    asm volatile("cp.async.cg.shared.global [%0], [%1], 16;" :: "r"(s), "l"(g));
}

// ---------------------------------------------------------------------------
// fp32 -> 3-split-bf16 interleave conversion (X:[h,h,l], W:[h,l,h])
// ---------------------------------------------------------------------------
struct ConvDesc { const float* in; unsigned short* out; int pairs; int isW; };

__global__ __launch_bounds__(256) void convert5(
    ConvDesc d0, ConvDesc d1, ConvDesc d2, ConvDesc d3, ConvDesc d4)
{
    ConvDesc d;
    switch (blockIdx.y) {
        case 0: d = d0; break; case 1: d = d1; break; case 2: d = d2; break;
        case 3: d = d3; break; default: d = d4; break;
    }
    int p = blockIdx.x * 256 + threadIdx.x;
    if (p >= d.pairs) return;
    float2 v = ((const float2*)d.in)[p];
    unsigned h0, l0, h1, l1;
    split2(v.x, h0, l0); split2(v.y, h1, l1);
    unsigned* o = (unsigned*)d.out + 3 * (size_t)p;
    if (d.isW) {
        o[0] = h0 | (l0 << 16); o[1] = h0 | (h1 << 16); o[2] = l1 | (h1 << 16);
    } else {
        o[0] = h0 | (h0 << 16); o[1] = l0 | (h1 << 16); o[2] = h1 | (l1 << 16);
    }
}

// ---------------------------------------------------------------------------
// bf16 TN GEMM, CTA 64x64, 128 threads (4 warps, 2m x 2n, warp tile 32x32),
// BKext=64, 3-stage cp.async pipeline, XOR-swizzled smem.
// splits==1: blockIdx.z selects one of two fused problems; direct store +bias.
// splits>1 : blockIdx.z = K-chunk; atomicAdd epilogue (bias pre-filled in Y).
// ---------------------------------------------------------------------------
#define GBK 64
#define ASTG 8192          // one A stage: 64 rows * 128B
#define NSTG 3

__global__ __launch_bounds__(128) void gemm_mma(
    const unsigned short* A0, const unsigned short* B0, const float* bias0,
    float* Y0, int Kx0, float osc0,
    const unsigned short* A1, const unsigned short* B1, const float* bias1,
    float* Y1, int Kx1, float osc1, int N, int splits)
{
    __shared__ __align__(16) unsigned char sm[NSTG * ASTG * 2];

    const unsigned short* A; const unsigned short* B;
    const float* bias; float* Y; int Kx; float osc; int koff;
    if (splits == 1) {
        if (blockIdx.z == 0) { A = A0; B = B0; bias = bias0; Y = Y0; Kx = Kx0; osc = osc0; }
        else                 { A = A1; B = B1; bias = bias1; Y = Y1; Kx = Kx1; osc = osc1; }
        koff = 0;
    } else {
        A = A0; B = B0; bias = bias0; Y = Y0; Kx = Kx0; osc = osc0;
        koff = blockIdx.z * (Kx0 / splits);
    }
    const int NT = (splits == 1 ? Kx : Kx / splits) / GBK;

    const int tid  = threadIdx.x;
    const int lane = tid & 31;
    const int wid  = tid >> 5;
    const int bm   = blockIdx.y * 64;
    const int bn   = blockIdx.x * 64;
    const int wm   = (wid & 1) * 32;
    const int wn   = (wid >> 1) * 32;

    const unsigned smBase = (unsigned)__cvta_generic_to_shared(sm);

    float acc[2][4][4];
#pragma unroll
    for (int i = 0; i < 2; i++)
#pragma unroll
        for (int j = 0; j < 4; j++)
#pragma unroll
            for (int r = 0; r < 4; r++) acc[i][j][r] = 0.f;

    // loader: thread covers granules g0..g0+3 of row lr (for both A and B)
    const int lr = tid >> 1;
    const int g0 = (tid & 1) * 4;
    const unsigned short* aG = A + (size_t)(bm + lr) * Kx + koff + g0 * 8;
    const unsigned short* bG = B + (size_t)(bn + lr) * Kx + koff + g0 * 8;
    const unsigned sRowA = smBase + lr * 128;
    const unsigned sRowB = smBase + NSTG * ASTG + lr * 128;
    const int rx = lr & 7;

#define LOAD_STAGE(KT, S)                                                     \
    {                                                                         \
        _Pragma("unroll")                                                     \
        for (int i = 0; i < 4; i++) {                                         \
            unsigned sw = (unsigned)(((g0 + i) ^ rx) << 4);                   \
            cpasync16(sRowA + (S) * ASTG + sw, aG + (KT) * GBK + i * 8);      \
            cpasync16(sRowB + (S) * ASTG + sw, bG + (KT) * GBK + i * 8);      \
        }                                                                     \
        asm volatile("cp.async.commit_group;");                               \
    }

    // ldmatrix per-lane address components
    const int arow = wm + (lane & 15);
    const int akg  = lane >> 4;
    const int brow = wn + (lane & 7) + ((lane >> 4) << 3);
    const int bkg  = (lane >> 3) & 1;
    const unsigned aOff0 = (unsigned)(arow * 128);
    const unsigned aOff1 = (unsigned)((arow + 16) * 128);
    const unsigned bOff0 = (unsigned)(brow * 128);
    const unsigned bOff1 = (unsigned)((brow + 16) * 128);
    const int ax = arow & 7;
    const int bx = brow & 7;

    LOAD_STAGE(0, 0);
    if (NT > 1) LOAD_STAGE(1, 1);
    if (NT > 2) LOAD_STAGE(2, 2);

    for (int kt = 0; kt < NT; kt++) {
        const int rem = NT - 1 - kt;
        if (rem >= 2)      asm volatile("cp.async.wait_group 2;");
        else if (rem == 1) asm volatile("cp.async.wait_group 1;");
        else               asm volatile("cp.async.wait_group 0;");
        __syncthreads();

        const int cur = kt % NSTG;
        const unsigned sA = smBase + cur * ASTG;
        const unsigned sB = smBase + NSTG * ASTG + cur * ASTG;
#pragma unroll
        for (int ks = 0; ks < 4; ks++) {
            unsigned ga = (unsigned)(((2 * ks + akg) ^ ax) << 4);
            unsigned gb = (unsigned)(((2 * ks + bkg) ^ bx) << 4);
            unsigned a0[4], a1[4], bb0[4], bb1[4];
            ldsm4(sA + aOff0 + ga, a0[0], a0[1], a0[2], a0[3]);
            ldsm4(sA + aOff1 + ga, a1[0], a1[1], a1[2], a1[3]);
            ldsm4(sB + bOff0 + gb, bb0[0], bb0[1], bb0[2], bb0[3]);
            ldsm4(sB + bOff1 + gb, bb1[0], bb1[1], bb1[2], bb1[3]);
            mma_bf16(acc[0][0], a0[0], a0[1], a0[2], a0[3], bb0[0], bb0[1]);
            mma_bf16(acc[0][1], a0[0], a0[1], a0[2], a0[3], bb0[2], bb0[3]);
            mma_bf16(acc[0][2], a0[0], a0[1], a0[2], a0[3], bb1[0], bb1[1]);
            mma_bf16(acc[0][3], a0[0], a0[1], a0[2], a0[3], bb1[2], bb1[3]);
            mma_bf16(acc[1][0], a1[0], a1[1], a1[2], a1[3], bb0[0], bb0[1]);
            mma_bf16(acc[1][1], a1[0], a1[1], a1[2], a1[3], bb0[2], bb0[3]);
            mma_bf16(acc[1][2], a1[0], a1[1], a1[2], a1[3], bb1[0], bb1[1]);
            mma_bf16(acc[1][3], a1[0], a1[1], a1[2], a1[3], bb1[2], bb1[3]);
        }
        __syncthreads();
        if (kt + NSTG < NT) LOAD_STAGE(kt + NSTG, cur);
    }
#undef LOAD_STAGE

    const int g  = lane >> 2;
    const int c2 = (lane & 3) * 2;
    if (splits == 1) {
#pragma unroll
        for (int mf = 0; mf < 2; mf++)
#pragma unroll
            for (int nf = 0; nf < 4; nf++) {
                int col = bn + wn + nf * 8 + c2;
                float2 bv = *(const float2*)(bias + col);
                int r0 = bm + wm + mf * 16 + g;
                float2 o0, o1;
                o0.x = (acc[mf][nf][0] + bv.x) * osc;
                o0.y = (acc[mf][nf][1] + bv.y) * osc;
                o1.x = (acc[mf][nf][2] + bv.x) * osc;
                o1.y = (acc[mf][nf][3] + bv.y) * osc;
                *(float2*)(Y + (size_t)r0 * N + col)       = o0;
                *(float2*)(Y + (size_t)(r0 + 8) * N + col) = o1;
            }
    } else {
#pragma unroll
        for (int mf = 0; mf < 2; mf++)
#pragma unroll
            for (int nf = 0; nf < 4; nf++) {
                int col = bn + wn + nf * 8 + c2;
                int r0 = bm + wm + mf * 16 + g;
                atomicAdd(Y + (size_t)r0 * N + col,           acc[mf][nf][0]);
                atomicAdd(Y + (size_t)r0 * N + col + 1,       acc[mf][nf][1]);
                atomicAdd(Y + (size_t)(r0 + 8) * N + col,     acc[mf][nf][2]);
                atomicAdd(Y + (size_t)(r0 + 8) * N + col + 1, acc[mf][nf][3]);
            }
    }
}

// ---------------------------------------------------------------------------
// Chebyshev attention; writes 3-split bf16 rows for GEMM3's A operand and
// pre-fills the output matrix with bias b3 (GEMM3 accumulates atomically).
// ---------------------------------------------------------------------------
#define NNODE 16
__global__ __launch_bounds__(512) void attn_cheb(
    const float* __restrict__ A, const float* __restrict__ T,
    const float* __restrict__ S, unsigned short* __restrict__ Mc,
    const float* __restrict__ b3, float* __restrict__ out)
{
    __shared__ float tex[HID], ssh[HID];
    __shared__ float rmin[16], rmax[16];
    __shared__ float nodeN[NNODE], nodeD[NNODE];
    __shared__ float cN[NNODE], cD[NNODE];
    __shared__ float mh[2];

    const int b = blockIdx.x;
    const int tid = threadIdx.x;
    const int lane = tid & 31;
    const int w = tid >> 5;

    if (tid < OUT_DIM) out[(size_t)b * OUT_DIM + tid] = b3[tid];

    tex[tid] = T[(size_t)b * HID + tid] * 1.44269504088896f;
    ssh[tid] = S[(size_t)b * HID + tid];
    float a = A[(size_t)b * HID + tid];

    float mn = a, mx = a;
#pragma unroll
    for (int o = 16; o; o >>= 1) {
        mn = fminf(mn, __shfl_xor_sync(0xffffffffu, mn, o));
        mx = fmaxf(mx, __shfl_xor_sync(0xffffffffu, mx, o));
    }
    if (lane == 0) { rmin[w] = mn; rmax[w] = mx; }
    __syncthreads();
    if (tid == 0) {
        float mn2 = rmin[0], mx2 = rmax[0];
#pragma unroll
        for (int i = 1; i < 16; i++) { mn2 = fminf(mn2, rmin[i]); mx2 = fmaxf(mx2, rmax[i]); }
        mh[0] = 0.5f * (mn2 + mx2);
        mh[1] = 0.5f * (mx2 - mn2) + 1e-12f;
    }
    __syncthreads();
    const float m = mh[0], h = mh[1];

    const float xk = fmaf(h, cospif((w + 0.5f) * (1.0f / NNODE)), m);
    float aN = 0.f, aD = 0.f;
#pragma unroll 8
    for (int j = lane; j < HID; j += 32) {
        float e = ex2f_(xk * tex[j]);
        aD += e;
        aN = fmaf(e, ssh[j], aN);
    }
#pragma unroll
    for (int o = 16; o; o >>= 1) {
        aN += __shfl_xor_sync(0xffffffffu, aN, o);
        aD += __shfl_xor_sync(0xffffffffu, aD, o);
    }
    if (lane == 0) { nodeN[w] = aN; nodeD[w] = aD; }
    __syncthreads();

    if (tid < 32) {
        const int n = tid & 15;
        const float* V = (tid < 16) ? nodeN : nodeD;
        float c = 0.f;
#pragma unroll
        for (int k = 0; k < NNODE; k++)
            c += V[k] * cospif((float)(n * (2 * k + 1)) * (1.0f / 32.0f));
        c *= (n == 0) ? (1.0f / NNODE) : (2.0f / NNODE);
        ((tid < 16) ? cN : cD)[n] = c;
    }
    __syncthreads();

    const float u = (a - m) * rcpf_(h);
    const float u2 = u + u;
    float bN1 = 0.f, bN2 = 0.f, bD1 = 0.f, bD2 = 0.f;
#pragma unroll
    for (int n = NNODE - 1; n >= 1; --n) {
        float tN = fmaf(u2, bN1, cN[n] - bN2);
        float tD = fmaf(u2, bD1, cD[n] - bD2);
        bN2 = bN1; bN1 = tN;
        bD2 = bD1; bD1 = tD;
    }
    float fN = fmaf(u, bN1, cN[0] - bN2);
    float fD = fmaf(u, bD1, cD[0] - bD2);
    float v = fN * rcpf_(fD);
    v = v > 0.f ? v : 0.f;

    unsigned hh, ll;
    split2(v, hh, ll);
    unsigned short* o = Mc + (size_t)b * KE2 + 3 * tid;
    o[0] = (unsigned short)hh; o[1] = (unsigned short)hh; o[2] = (unsigned short)ll;
}

extern "C" void kernel_launch(void* const* d_in, const int* in_sizes, int n_in,
                              void* d_out, int out_size)
{
    const float* combin = (const float*)d_in[0];
    const float* s_emb  = (const float*)d_in[1];
    const float* W1     = (const float*)d_in[2];
    const float* b1     = (const float*)d_in[3];
    const float* W2     = (const float*)d_in[4];
    const float* b2     = (const float*)d_in[5];
    const float* W3     = (const float*)d_in[6];
    const float* b3     = (const float*)d_in[7];
    float* out = (float*)d_out;

    float *A, *T;
    unsigned short *Xc1, *Xc2, *Wc1, *Wc2, *Wc3, *Mc;
    cudaGetSymbolAddress((void**)&A,   g_A);
    cudaGetSymbolAddress((void**)&T,   g_T);
    cudaGetSymbolAddress((void**)&Xc1, g_Xc1);
    cudaGetSymbolAddress((void**)&Xc2, g_Xc2);
    cudaGetSymbolAddress((void**)&Wc1, g_Wc1);
    cudaGetSymbolAddress((void**)&Wc2, g_Wc2);
    cudaGetSymbolAddress((void**)&Wc3, g_Wc3);
    cudaGetSymbolAddress((void**)&Mc,  g_Mc);

    const float sigma = 0.044194173824159216f;  // 1/sqrt(512)

    ConvDesc d0 = { combin, Xc1, BATCH * IN_DIM / 2, 0 };
    ConvDesc d1 = { s_emb,  Xc2, BATCH * HID / 2,    0 };
    ConvDesc d2 = { W2,     Wc1, HID * IN_DIM / 2,   1 };
    ConvDesc d3 = { W1,     Wc2, HID * HID / 2,      1 };
    ConvDesc d4 = { W3,     Wc3, OUT_DIM * HID / 2,  1 };
    convert5<<<dim3(BATCH * IN_DIM / 2 / 256, 5), 256>>>(d0, d1, d2, d3, d4);

    // GEMM1 + GEMM2 fused (z = problem): 8 x 16 x 2 = 256 CTAs
    gemm_mma<<<dim3(HID / 64, BATCH / 64, 2), 128>>>(
        Xc1, Wc1, b2, A, KE1, sigma,
        Xc2, Wc2, b1, T, KE2, 1.0f, HID, 1);

    attn_cheb<<<BATCH, 512>>>(A, T, s_emb, Mc, b3, out);

    // GEMM3 split-K=3 (z = k-chunk): 4 x 16 x 3 = 192 CTAs, atomic accumulate
    gemm_mma<<<dim3(OUT_DIM / 64, BATCH / 64, 3), 128>>>(
        Mc, Wc3, b3, out, KE2, 1.0f,
        Mc, Wc3, b3, out, KE2, 1.0f, OUT_DIM, 3);
}

// round 10
// speedup vs baseline: 1.3734x; 1.0526x over previous
#include <cuda_runtime.h>
#include <cuda_bf16.h>
#include <math.h>

#define BATCH   1024
#define IN_DIM  768
#define HID     512
#define OUT_DIM 256
#define KE1     (IN_DIM * 3)   // 2304 ext
#define KE2     (HID * 3)      // 1536 ext

// ---- scratch (__device__ globals; allocation-free rule) ----
__device__ float          g_A[BATCH * HID];
__device__ float          g_T[BATCH * HID];
__device__ unsigned short g_Xc1[BATCH * KE1];     // combin split [h,h,l]
__device__ unsigned short g_Xc2[BATCH * KE2];     // s_emb  split [h,h,l]
__device__ unsigned short g_Wc1[HID * KE1];       // W2 split [h,l,h]
__device__ unsigned short g_Wc2[HID * KE2];       // W1 split [h,l,h]
__device__ unsigned short g_Wc3[OUT_DIM * KE2];   // W3 split [h,l,h]
__device__ unsigned short g_Mc[BATCH * KE2];      // attn out split [h,h,l]

__device__ __forceinline__ float ex2f_(float x) {
    float y; asm("ex2.approx.f32 %0, %1;" : "=f"(y) : "f"(x)); return y;
}
__device__ __forceinline__ float rcpf_(float x) {
    float y; asm("rcp.approx.f32 %0, %1;" : "=f"(y) : "f"(x)); return y;
}
__device__ __forceinline__ void split2(float v, unsigned &h, unsigned &l) {
    __nv_bfloat16 hb = __float2bfloat16(v);
    float lo = v - __bfloat162float(hb);
    h = (unsigned)__bfloat16_as_ushort(hb);
    l = (unsigned)__bfloat16_as_ushort(__float2bfloat16(lo));
}
__device__ __forceinline__ void ldsm4(unsigned addr, unsigned &r0, unsigned &r1,
                                      unsigned &r2, unsigned &r3) {
    asm volatile("ldmatrix.sync.aligned.m8n8.x4.shared.b16 {%0,%1,%2,%3}, [%4];"
                 : "=r"(r0), "=r"(r1), "=r"(r2), "=r"(r3) : "r"(addr));
}
__device__ __forceinline__ void mma_bf16(float c[4], unsigned a0, unsigned a1,
                                         unsigned a2, unsigned a3,
                                         unsigned b0, unsigned b1) {
    asm volatile(
        "mma.sync.aligned.m16n8k16.row.col.f32.bf16.bf16.f32 "
        "{%0,%1,%2,%3}, {%4,%5,%6,%7}, {%8,%9}, {%0,%1,%2,%3};\n"
        : "+f"(c[0]), "+f"(c[1]), "+f"(c[2]), "+f"(c[3])
        : "r"(a0), "r"(a1), "r"(a2), "r"(a3), "r"(b0), "r"(b1));
}
__device__ __forceinline__ void cpasync16(unsigned s, const void* g) {
    asm volatile("cp.async.cg.shared.global [%0], [%1], 16;" :: "r"(s), "l"(g));
}

// ---------------------------------------------------------------------------
// fp32 -> 3-split-bf16 interleave conversion (X:[h,h,l], W:[h,l,h]).
// One float4 (2 pairs) per thread.
// ---------------------------------------------------------------------------
struct ConvDesc { const float* in; unsigned short* out; int quads; int isW; };

__global__ __launch_bounds__(256) void convert5(
    ConvDesc d0, ConvDesc d1, ConvDesc d2, ConvDesc d3, ConvDesc d4)
{
    ConvDesc d;
    switch (blockIdx.y) {
        case 0: d = d0; break; case 1: d = d1; break; case 2: d = d2; break;
        case 3: d = d3; break; default: d = d4; break;
    }
    int q = blockIdx.x * 256 + threadIdx.x;
    if (q >= d.quads) return;
    float4 v = ((const float4*)d.in)[q];
    unsigned h0, l0, h1, l1, h2, l2, h3, l3;
    split2(v.x, h0, l0); split2(v.y, h1, l1);
    split2(v.z, h2, l2); split2(v.w, h3, l3);
    unsigned* o = (unsigned*)d.out + 6 * (size_t)q;
    if (d.isW) {
        o[0] = h0 | (l0 << 16); o[1] = h0 | (h1 << 16); o[2] = l1 | (h1 << 16);
        o[3] = h2 | (l2 << 16); o[4] = h2 | (h3 << 16); o[5] = l3 | (h3 << 16);
    } else {
        o[0] = h0 | (h0 << 16); o[1] = l0 | (h1 << 16); o[2] = h1 | (l1 << 16);
        o[3] = h2 | (h2 << 16); o[4] = l2 | (h3 << 16); o[5] = h3 | (l3 << 16);
    }
}

// ---------------------------------------------------------------------------
// bf16 TN GEMM, CTA 64x64, 256 threads (8 warps, 4m x 2n, warp tile 16x32),
// BKext=64, 3-stage cp.async pipeline, XOR-swizzled smem.
// splits==1: blockIdx.z selects one of two fused problems; direct store +bias.
// splits>1 : blockIdx.z = K-chunk; atomicAdd epilogue (bias pre-filled in Y).
// ---------------------------------------------------------------------------
#define GBK 64
#define ASTG 8192          // one stage: 64 rows * 128B
#define NSTG 3

__global__ __launch_bounds__(256) void gemm_mma(
    const unsigned short* A0, const unsigned short* B0, const float* bias0,
    float* Y0, int Kx0, float osc0,
    const unsigned short* A1, const unsigned short* B1, const float* bias1,
    float* Y1, int Kx1, float osc1, int N, int splits)
{
    __shared__ __align__(16) unsigned char sm[NSTG * ASTG * 2];

    const unsigned short* A; const unsigned short* B;
    const float* bias; float* Y; int Kx; float osc; int koff;
    if (splits == 1) {
        if (blockIdx.z == 0) { A = A0; B = B0; bias = bias0; Y = Y0; Kx = Kx0; osc = osc0; }
        else                 { A = A1; B = B1; bias = bias1; Y = Y1; Kx = Kx1; osc = osc1; }
        koff = 0;
    } else {
        A = A0; B = B0; bias = bias0; Y = Y0; Kx = Kx0; osc = osc0;
        koff = blockIdx.z * (Kx0 / splits);
    }
    const int NT = (splits == 1 ? Kx : Kx / splits) / GBK;

    const int tid  = threadIdx.x;
    const int lane = tid & 31;
    const int wid  = tid >> 5;
    const int bm   = blockIdx.y * 64;
    const int bn   = blockIdx.x * 64;
    const int wm   = (wid & 3) * 16;     // 0,16,32,48
    const int wn   = (wid >> 2) * 32;    // 0,32

    const unsigned smBase = (unsigned)__cvta_generic_to_shared(sm);

    float acc[4][4];
#pragma unroll
    for (int j = 0; j < 4; j++)
#pragma unroll
        for (int r = 0; r < 4; r++) acc[j][r] = 0.f;

    // loader: thread covers granules g0,g0+1 of row lr (A and B each)
    const int lr = tid >> 2;
    const int g0 = (tid & 3) * 2;
    const unsigned short* aG = A + (size_t)(bm + lr) * Kx + koff + g0 * 8;
    const unsigned short* bG = B + (size_t)(bn + lr) * Kx + koff + g0 * 8;
    const unsigned sw0 = (unsigned)(((g0 + 0) ^ (lr & 7)) << 4);
    const unsigned sw1 = (unsigned)(((g0 + 1) ^ (lr & 7)) << 4);
    const unsigned sRowA = smBase + lr * 128;
    const unsigned sRowB = smBase + NSTG * ASTG + lr * 128;

#define LOAD_STAGE(KT, S)                                                     \
    {                                                                         \
        cpasync16(sRowA + (S) * ASTG + sw0, aG + (KT) * GBK + 0);             \
        cpasync16(sRowA + (S) * ASTG + sw1, aG + (KT) * GBK + 8);             \
        cpasync16(sRowB + (S) * ASTG + sw0, bG + (KT) * GBK + 0);             \
        cpasync16(sRowB + (S) * ASTG + sw1, bG + (KT) * GBK + 8);             \
        asm volatile("cp.async.commit_group;");                               \
    }

    // ldmatrix per-lane address components
    const int arow = wm + (lane & 15);
    const int akg  = lane >> 4;
    const int brow = wn + (lane & 7) + ((lane >> 4) << 3);
    const int bkg  = (lane >> 3) & 1;
    const unsigned aOff  = (unsigned)(arow * 128);
    const unsigned bOff0 = (unsigned)(brow * 128);
    const unsigned bOff1 = (unsigned)((brow + 16) * 128);
    const int ax = arow & 7;
    const int bx = brow & 7;

    LOAD_STAGE(0, 0);
    if (NT > 1) LOAD_STAGE(1, 1);
    if (NT > 2) LOAD_STAGE(2, 2);

    for (int kt = 0; kt < NT; kt++) {
        const int rem = NT - 1 - kt;
        if (rem >= 2)      asm volatile("cp.async.wait_group 2;");
        else if (rem == 1) asm volatile("cp.async.wait_group 1;");
        else               asm volatile("cp.async.wait_group 0;");
        __syncthreads();

        const int cur = kt % NSTG;
        const unsigned sA = smBase + cur * ASTG;
        const unsigned sB = smBase + NSTG * ASTG + cur * ASTG;
#pragma unroll
        for (int ks = 0; ks < 4; ks++) {
            unsigned ga = (unsigned)(((2 * ks + akg) ^ ax) << 4);
            unsigned gb = (unsigned)(((2 * ks + bkg) ^ bx) << 4);
            unsigned a[4], bb0[4], bb1[4];
            ldsm4(sA + aOff + ga, a[0], a[1], a[2], a[3]);
            ldsm4(sB + bOff0 + gb, bb0[0], bb0[1], bb0[2], bb0[3]);
            ldsm4(sB + bOff1 + gb, bb1[0], bb1[1], bb1[2], bb1[3]);
            mma_bf16(acc[0], a[0], a[1], a[2], a[3], bb0[0], bb0[1]);
            mma_bf16(acc[1], a[0], a[1], a[2], a[3], bb0[2], bb0[3]);
            mma_bf16(acc[2], a[0], a[1], a[2], a[3], bb1[0], bb1[1]);
            mma_bf16(acc[3], a[0], a[1], a[2], a[3], bb1[2], bb1[3]);
        }
        __syncthreads();
        if (kt + NSTG < NT) LOAD_STAGE(kt + NSTG, cur);
    }
#undef LOAD_STAGE

    const int g  = lane >> 2;
    const int c2 = (lane & 3) * 2;
    if (splits == 1) {
#pragma unroll
        for (int nf = 0; nf < 4; nf++) {
            int col = bn + wn + nf * 8 + c2;
            float2 bv = *(const float2*)(bias + col);
            int r0 = bm + wm + g;
            float2 o0, o1;
            o0.x = (acc[nf][0] + bv.x) * osc;
            o0.y = (acc[nf][1] + bv.y) * osc;
            o1.x = (acc[nf][2] + bv.x) * osc;
            o1.y = (acc[nf][3] + bv.y) * osc;
            *(float2*)(Y + (size_t)r0 * N + col)       = o0;
            *(float2*)(Y + (size_t)(r0 + 8) * N + col) = o1;
        }
    } else {
#pragma unroll
        for (int nf = 0; nf < 4; nf++) {
            int col = bn + wn + nf * 8 + c2;
            int r0 = bm + wm + g;
            atomicAdd(Y + (size_t)r0 * N + col,           acc[nf][0]);
            atomicAdd(Y + (size_t)r0 * N + col + 1,       acc[nf][1]);
            atomicAdd(Y + (size_t)(r0 + 8) * N + col,     acc[nf][2]);
            atomicAdd(Y + (size_t)(r0 + 8) * N + col + 1, acc[nf][3]);
        }
    }
}

// ---------------------------------------------------------------------------
// Chebyshev attention; writes 3-split bf16 rows for GEMM3's A operand and
// pre-fills the output matrix with bias b3 (GEMM3 accumulates atomically).
// ---------------------------------------------------------------------------
#define NNODE 16
__global__ __launch_bounds__(512) void attn_cheb(
    const float* __restrict__ A, const float* __restrict__ T,
    const float* __restrict__ S, unsigned short* __restrict__ Mc,
    const float* __restrict__ b3, float* __restrict__ out)
{
    __shared__ float tex[HID], ssh[HID];
    __shared__ float rmin[16], rmax[16];
    __shared__ float nodeN[NNODE], nodeD[NNODE];
    __shared__ float cN[NNODE], cD[NNODE];
    __shared__ float mh[2];

    const int b = blockIdx.x;
    const int tid = threadIdx.x;
    const int lane = tid & 31;
    const int w = tid >> 5;

    if (tid < OUT_DIM) out[(size_t)b * OUT_DIM + tid] = b3[tid];

    tex[tid] = T[(size_t)b * HID + tid] * 1.44269504088896f;
    ssh[tid] = S[(size_t)b * HID + tid];
    float a = A[(size_t)b * HID + tid];

    float mn = a, mx = a;
#pragma unroll
    for (int o = 16; o; o >>= 1) {
        mn = fminf(mn, __shfl_xor_sync(0xffffffffu, mn, o));
        mx = fmaxf(mx, __shfl_xor_sync(0xffffffffu, mx, o));
    }
    if (lane == 0) { rmin[w] = mn; rmax[w] = mx; }
    __syncthreads();
    if (tid == 0) {
        float mn2 = rmin[0], mx2 = rmax[0];
#pragma unroll
        for (int i = 1; i < 16; i++) { mn2 = fminf(mn2, rmin[i]); mx2 = fmaxf(mx2, rmax[i]); }
        mh[0] = 0.5f * (mn2 + mx2);
        mh[1] = 0.5f * (mx2 - mn2) + 1e-12f;
    }
    __syncthreads();
    const float m = mh[0], h = mh[1];

    const float xk = fmaf(h, cospif((w + 0.5f) * (1.0f / NNODE)), m);
    float aN = 0.f, aD = 0.f;
#pragma unroll 8
    for (int j = lane; j < HID; j += 32) {
        float e = ex2f_(xk * tex[j]);
        aD += e;
        aN = fmaf(e, ssh[j], aN);
    }
#pragma unroll
    for (int o = 16; o; o >>= 1) {
        aN += __shfl_xor_sync(0xffffffffu, aN, o);
        aD += __shfl_xor_sync(0xffffffffu, aD, o);
    }
    if (lane == 0) { nodeN[w] = aN; nodeD[w] = aD; }
    __syncthreads();

    if (tid < 32) {
        const int n = tid & 15;
        const float* V = (tid < 16) ? nodeN : nodeD;
        float c = 0.f;
#pragma unroll
        for (int k = 0; k < NNODE; k++)
            c += V[k] * cospif((float)(n * (2 * k + 1)) * (1.0f / 32.0f));
        c *= (n == 0) ? (1.0f / NNODE) : (2.0f / NNODE);
        ((tid < 16) ? cN : cD)[n] = c;
    }
    __syncthreads();

    const float u = (a - m) * rcpf_(h);
    const float u2 = u + u;
    float bN1 = 0.f, bN2 = 0.f, bD1 = 0.f, bD2 = 0.f;
#pragma unroll
    for (int n = NNODE - 1; n >= 1; --n) {
        float tN = fmaf(u2, bN1, cN[n] - bN2);
        float tD = fmaf(u2, bD1, cD[n] - bD2);
        bN2 = bN1; bN1 = tN;
        bD2 = bD1; bD1 = tD;
    }
    float fN = fmaf(u, bN1, cN[0] - bN2);
    float fD = fmaf(u, bD1, cD[0] - bD2);
    float v = fN * rcpf_(fD);
    v = v > 0.f ? v : 0.f;

    unsigned hh, ll;
    split2(v, hh, ll);
    unsigned short* o = Mc + (size_t)b * KE2 + 3 * tid;
    o[0] = (unsigned short)hh; o[1] = (unsigned short)hh; o[2] = (unsigned short)ll;
}

extern "C" void kernel_launch(void* const* d_in, const int* in_sizes, int n_in,
                              void* d_out, int out_size)
{
    const float* combin = (const float*)d_in[0];
    const float* s_emb  = (const float*)d_in[1];
    const float* W1     = (const float*)d_in[2];
    const float* b1     = (const float*)d_in[3];
    const float* W2     = (const float*)d_in[4];
    const float* b2     = (const float*)d_in[5];
    const float* W3     = (const float*)d_in[6];
    const float* b3     = (const float*)d_in[7];
    float* out = (float*)d_out;

    float *A, *T;
    unsigned short *Xc1, *Xc2, *Wc1, *Wc2, *Wc3, *Mc;
    cudaGetSymbolAddress((void**)&A,   g_A);
    cudaGetSymbolAddress((void**)&T,   g_T);
    cudaGetSymbolAddress((void**)&Xc1, g_Xc1);
    cudaGetSymbolAddress((void**)&Xc2, g_Xc2);
    cudaGetSymbolAddress((void**)&Wc1, g_Wc1);
    cudaGetSymbolAddress((void**)&Wc2, g_Wc2);
    cudaGetSymbolAddress((void**)&Wc3, g_Wc3);
    cudaGetSymbolAddress((void**)&Mc,  g_Mc);

    const float sigma = 0.044194173824159216f;  // 1/sqrt(512)

    ConvDesc d0 = { combin, Xc1, BATCH * IN_DIM / 4, 0 };
    ConvDesc d1 = { s_emb,  Xc2, BATCH * HID / 4,    0 };
    ConvDesc d2 = { W2,     Wc1, HID * IN_DIM / 4,   1 };
    ConvDesc d3 = { W1,     Wc2, HID * HID / 4,      1 };
    ConvDesc d4 = { W3,     Wc3, OUT_DIM * HID / 4,  1 };
    convert5<<<dim3(BATCH * IN_DIM / 4 / 256, 5), 256>>>(d0, d1, d2, d3, d4);

    // GEMM1 + GEMM2 fused (z = problem): 8 x 16 x 2 = 256 CTAs, 8 warps each
    gemm_mma<<<dim3(HID / 64, BATCH / 64, 2), 256>>>(
        Xc1, Wc1, b2, A, KE1, sigma,
        Xc2, Wc2, b1, T, KE2, 1.0f, HID, 1);

    attn_cheb<<<BATCH, 512>>>(A, T, s_emb, Mc, b3, out);

    // GEMM3 split-K=6 (z = k-chunk): 4 x 16 x 6 = 384 CTAs, atomic accumulate
    gemm_mma<<<dim3(OUT_DIM / 64, BATCH / 64, 6), 256>>>(
        Mc, Wc3, b3, out, KE2, 1.0f,
        Mc, Wc3, b3, out, KE2, 1.0f, OUT_DIM, 6);
}

// round 11
// speedup vs baseline: 1.4133x; 1.0290x over previous
#include <cuda_runtime.h>
#include <cuda_bf16.h>
#include <math.h>

#define BATCH   1024
#define IN_DIM  768
#define HID     512
#define OUT_DIM 256
#define KE1     (IN_DIM * 3)   // 2304 ext
#define KE2     (HID * 3)      // 1536 ext

// ---- scratch (__device__ globals; allocation-free rule) ----
__device__ float          g_A[BATCH * HID];
__device__ float          g_T[BATCH * HID];
__device__ unsigned short g_Xc1[BATCH * KE1];     // combin split [h,h,l]
__device__ unsigned short g_Xc2[BATCH * KE2];     // s_emb  split [h,h,l]
__device__ unsigned short g_Wc1[HID * KE1];       // W2 split [h,l,h]
__device__ unsigned short g_Wc2[HID * KE2];       // W1 split [h,l,h]
__device__ unsigned short g_Wc3[OUT_DIM * KE2];   // W3 split [h,l,h]
__device__ unsigned short g_Mc[BATCH * KE2];      // attn out split [h,h,l]

__device__ __forceinline__ float ex2f_(float x) {
    float y; asm("ex2.approx.f32 %0, %1;" : "=f"(y) : "f"(x)); return y;
}
__device__ __forceinline__ float rcpf_(float x) {
    float y; asm("rcp.approx.f32 %0, %1;" : "=f"(y) : "f"(x)); return y;
}
__device__ __forceinline__ void split2(float v, unsigned &h, unsigned &l) {
    __nv_bfloat16 hb = __float2bfloat16(v);
    float lo = v - __bfloat162float(hb);
    h = (unsigned)__bfloat16_as_ushort(hb);
    l = (unsigned)__bfloat16_as_ushort(__float2bfloat16(lo));
}
__device__ __forceinline__ void ldsm4(unsigned addr, unsigned &r0, unsigned &r1,
                                      unsigned &r2, unsigned &r3) {
    asm volatile("ldmatrix.sync.aligned.m8n8.x4.shared.b16 {%0,%1,%2,%3}, [%4];"
                 : "=r"(r0), "=r"(r1), "=r"(r2), "=r"(r3) : "r"(addr));
}
__device__ __forceinline__ void mma_bf16(float c[4], unsigned a0, unsigned a1,
                                         unsigned a2, unsigned a3,
                                         unsigned b0, unsigned b1) {
    asm volatile(
        "mma.sync.aligned.m16n8k16.row.col.f32.bf16.bf16.f32 "
        "{%0,%1,%2,%3}, {%4,%5,%6,%7}, {%8,%9}, {%0,%1,%2,%3};\n"
        : "+f"(c[0]), "+f"(c[1]), "+f"(c[2]), "+f"(c[3])
        : "r"(a0), "r"(a1), "r"(a2), "r"(a3), "r"(b0), "r"(b1));
}
__device__ __forceinline__ void cpasync16(unsigned s, const void* g) {
    asm volatile("cp.async.cg.shared.global [%0], [%1], 16;" :: "r"(s), "l"(g));
}

// ---------------------------------------------------------------------------
// fp32 -> 3-split-bf16 interleave (X:[h,h,l], W:[h,l,h]); also pre-fills the
// A and T accumulators with their (scaled) biases for the atomic GEMM.
// ---------------------------------------------------------------------------
struct ConvDesc { const float* in; unsigned short* out; int quads; int isW; };

__global__ __launch_bounds__(256) void convert5(
    ConvDesc d0, ConvDesc d1, ConvDesc d2, ConvDesc d3, ConvDesc d4,
    const float* __restrict__ b1, const float* __restrict__ b2,
    float* __restrict__ A, float* __restrict__ T, float sigma)
{
    int q = blockIdx.x * 256 + threadIdx.x;

    if (blockIdx.y >= 5) {
        // bias pre-fill: A[r][c] = b2[c]*sigma ; T[r][c] = b1[c]
        if (q >= BATCH * HID / 4) return;
        int c = (q * 4) & (HID - 1);
        float4 v;
        if (blockIdx.y == 5) {
            v.x = b2[c] * sigma; v.y = b2[c + 1] * sigma;
            v.z = b2[c + 2] * sigma; v.w = b2[c + 3] * sigma;
            ((float4*)A)[q] = v;
        } else {
            v.x = b1[c]; v.y = b1[c + 1]; v.z = b1[c + 2]; v.w = b1[c + 3];
            ((float4*)T)[q] = v;
        }
        return;
    }

    ConvDesc d;
    switch (blockIdx.y) {
        case 0: d = d0; break; case 1: d = d1; break; case 2: d = d2; break;
        case 3: d = d3; break; default: d = d4; break;
    }
    if (q >= d.quads) return;
    float4 v = ((const float4*)d.in)[q];
    unsigned h0, l0, h1, l1, h2, l2, h3, l3;
    split2(v.x, h0, l0); split2(v.y, h1, l1);
    split2(v.z, h2, l2); split2(v.w, h3, l3);
    unsigned* o = (unsigned*)d.out + 6 * (size_t)q;
    if (d.isW) {
        o[0] = h0 | (l0 << 16); o[1] = h0 | (h1 << 16); o[2] = l1 | (h1 << 16);
        o[3] = h2 | (l2 << 16); o[4] = h2 | (h3 << 16); o[5] = l3 | (h3 << 16);
    } else {
        o[0] = h0 | (h0 << 16); o[1] = l0 | (h1 << 16); o[2] = h1 | (l1 << 16);
        o[3] = h2 | (h2 << 16); o[4] = l2 | (h3 << 16); o[5] = h3 | (l3 << 16);
    }
}

// ---------------------------------------------------------------------------
// bf16 TN GEMM, CTA 64x64, 256 threads (8 warps, 4m x 2n, warp tile 16x32),
// BKext=64, 4-stage single-barrier cp.async pipeline, fragment double-buffer.
// blockIdx.z = problem * splits + k-chunk. Epilogue: atomicAdd(acc*osc) into Y
// (bias pre-filled by producer). Y poisoned? out is prefilled by attn kernel.
// ---------------------------------------------------------------------------
#define GBK 64
#define ASTG 8192          // one stage: 64 rows * 128B
#define NSTG 4

__global__ __launch_bounds__(256, 2) void gemm_mma(
    const unsigned short* A0, const unsigned short* B0, float* Y0, int Kx0, float osc0,
    const unsigned short* A1, const unsigned short* B1, float* Y1, int Kx1, float osc1,
    int N, int splits)
{
    __shared__ __align__(16) unsigned char sm[NSTG * ASTG * 2];

    const int prob  = blockIdx.z / splits;
    const int chunk = blockIdx.z % splits;

    const unsigned short* A; const unsigned short* B; float* Y; int Kx; float osc;
    if (prob == 0) { A = A0; B = B0; Y = Y0; Kx = Kx0; osc = osc0; }
    else           { A = A1; B = B1; Y = Y1; Kx = Kx1; osc = osc1; }
    const int koff = chunk * (Kx / splits);
    const int NT   = (Kx / splits) / GBK;

    const int tid  = threadIdx.x;
    const int lane = tid & 31;
    const int wid  = tid >> 5;
    const int bm   = blockIdx.y * 64;
    const int bn   = blockIdx.x * 64;
    const int wm   = (wid & 3) * 16;     // 0,16,32,48
    const int wn   = (wid >> 2) * 32;    // 0,32

    const unsigned smBase = (unsigned)__cvta_generic_to_shared(sm);

    float acc[4][4];
#pragma unroll
    for (int j = 0; j < 4; j++)
#pragma unroll
        for (int r = 0; r < 4; r++) acc[j][r] = 0.f;

    // loader: thread covers granules g0,g0+1 of row lr (A and B each)
    const int lr = tid >> 2;
    const int g0 = (tid & 3) * 2;
    const unsigned short* aG = A + (size_t)(bm + lr) * Kx + koff + g0 * 8;
    const unsigned short* bG = B + (size_t)(bn + lr) * Kx + koff + g0 * 8;
    const unsigned sw0 = (unsigned)(((g0 + 0) ^ (lr & 7)) << 4);
    const unsigned sw1 = (unsigned)(((g0 + 1) ^ (lr & 7)) << 4);
    const unsigned sRowA = smBase + lr * 128;
    const unsigned sRowB = smBase + NSTG * ASTG + lr * 128;

#define LOAD_STAGE(KT, S)                                                     \
    {                                                                         \
        cpasync16(sRowA + (S) * ASTG + sw0, aG + (KT) * GBK + 0);             \
        cpasync16(sRowA + (S) * ASTG + sw1, aG + (KT) * GBK + 8);             \
        cpasync16(sRowB + (S) * ASTG + sw0, bG + (KT) * GBK + 0);             \
        cpasync16(sRowB + (S) * ASTG + sw1, bG + (KT) * GBK + 8);             \
    }

    // ldmatrix per-lane address components
    const int arow = wm + (lane & 15);
    const int akg  = lane >> 4;
    const int brow = wn + (lane & 7) + ((lane >> 4) << 3);
    const int bkg  = (lane >> 3) & 1;
    const unsigned aOff  = (unsigned)(arow * 128);
    const unsigned bOff0 = (unsigned)(brow * 128);
    const unsigned bOff1 = (unsigned)((brow + 16) * 128);
    const int ax = arow & 7;
    const int bx = brow & 7;

    LOAD_STAGE(0, 0); asm volatile("cp.async.commit_group;");
    LOAD_STAGE(1, 1); asm volatile("cp.async.commit_group;");
    LOAD_STAGE(2, 2); asm volatile("cp.async.commit_group;");

    unsigned af[2][4], bf0[2][4], bf1[2][4];

#define LDFRAG(KS, BUF, SA, SB)                                               \
    {                                                                         \
        unsigned ga = (unsigned)(((2 * (KS) + akg) ^ ax) << 4);               \
        unsigned gb = (unsigned)(((2 * (KS) + bkg) ^ bx) << 4);               \
        ldsm4((SA) + aOff  + ga, af[BUF][0],  af[BUF][1],  af[BUF][2],  af[BUF][3]);  \
        ldsm4((SB) + bOff0 + gb, bf0[BUF][0], bf0[BUF][1], bf0[BUF][2], bf0[BUF][3]); \
        ldsm4((SB) + bOff1 + gb, bf1[BUF][0], bf1[BUF][1], bf1[BUF][2], bf1[BUF][3]); \
    }
#define DOMMA(BUF)                                                            \
    {                                                                         \
        mma_bf16(acc[0], af[BUF][0], af[BUF][1], af[BUF][2], af[BUF][3], bf0[BUF][0], bf0[BUF][1]); \
        mma_bf16(acc[1], af[BUF][0], af[BUF][1], af[BUF][2], af[BUF][3], bf0[BUF][2], bf0[BUF][3]); \
        mma_bf16(acc[2], af[BUF][0], af[BUF][1], af[BUF][2], af[BUF][3], bf1[BUF][0], bf1[BUF][1]); \
        mma_bf16(acc[3], af[BUF][0], af[BUF][1], af[BUF][2], af[BUF][3], bf1[BUF][2], bf1[BUF][3]); \
    }

    for (int kt = 0; kt < NT; kt++) {
        // group kt must be complete; <=2 younger groups may stay pending
        asm volatile("cp.async.wait_group 2;");
        __syncthreads();
        // refill stage (kt+3)%NSTG: its last readers ran in iter kt-1, and the
        // barrier above guarantees they are done.
        if (kt + 3 < NT) LOAD_STAGE(kt + 3, (kt + 3) & (NSTG - 1));
        asm volatile("cp.async.commit_group;");

        const unsigned sA = smBase + (kt & (NSTG - 1)) * ASTG;
        const unsigned sB = smBase + NSTG * ASTG + (kt & (NSTG - 1)) * ASTG;
        LDFRAG(0, 0, sA, sB);
#pragma unroll
        for (int ks = 0; ks < 4; ks++) {
            if (ks < 3) LDFRAG(ks + 1, (ks + 1) & 1, sA, sB);
            DOMMA(ks & 1);
        }
    }
#undef LOAD_STAGE
#undef LDFRAG
#undef DOMMA

    const int g  = lane >> 2;
    const int c2 = (lane & 3) * 2;
#pragma unroll
    for (int nf = 0; nf < 4; nf++) {
        int col = bn + wn + nf * 8 + c2;
        int r0 = bm + wm + g;
        atomicAdd(Y + (size_t)r0 * N + col,           acc[nf][0] * osc);
        atomicAdd(Y + (size_t)r0 * N + col + 1,       acc[nf][1] * osc);
        atomicAdd(Y + (size_t)(r0 + 8) * N + col,     acc[nf][2] * osc);
        atomicAdd(Y + (size_t)(r0 + 8) * N + col + 1, acc[nf][3] * osc);
    }
}

// ---------------------------------------------------------------------------
// Chebyshev attention; writes 3-split bf16 rows for GEMM3's A operand and
// pre-fills the output matrix with bias b3 (GEMM3 accumulates atomically).
// ---------------------------------------------------------------------------
#define NNODE 16
__global__ __launch_bounds__(512) void attn_cheb(
    const float* __restrict__ A, const float* __restrict__ T,
    const float* __restrict__ S, unsigned short* __restrict__ Mc,
    const float* __restrict__ b3, float* __restrict__ out)
{
    __shared__ float tex[HID], ssh[HID];
    __shared__ float rmin[16], rmax[16];
    __shared__ float nodeN[NNODE], nodeD[NNODE];
    __shared__ float cN[NNODE], cD[NNODE];
    __shared__ float mh[2];

    const int b = blockIdx.x;
    const int tid = threadIdx.x;
    const int lane = tid & 31;
    const int w = tid >> 5;

    if (tid < OUT_DIM) out[(size_t)b * OUT_DIM + tid] = b3[tid];

    tex[tid] = T[(size_t)b * HID + tid] * 1.44269504088896f;
    ssh[tid] = S[(size_t)b * HID + tid];
    float a = A[(size_t)b * HID + tid];

    float mn = a, mx = a;
#pragma unroll
    for (int o = 16; o; o >>= 1) {
        mn = fminf(mn, __shfl_xor_sync(0xffffffffu, mn, o));
        mx = fmaxf(mx, __shfl_xor_sync(0xffffffffu, mx, o));
    }
    if (lane == 0) { rmin[w] = mn; rmax[w] = mx; }
    __syncthreads();
    if (tid == 0) {
        float mn2 = rmin[0], mx2 = rmax[0];
#pragma unroll
        for (int i = 1; i < 16; i++) { mn2 = fminf(mn2, rmin[i]); mx2 = fmaxf(mx2, rmax[i]); }
        mh[0] = 0.5f * (mn2 + mx2);
        mh[1] = 0.5f * (mx2 - mn2) + 1e-12f;
    }
    __syncthreads();
    const float m = mh[0], h = mh[1];

    const float xk = fmaf(h, cospif((w + 0.5f) * (1.0f / NNODE)), m);
    float aN = 0.f, aD = 0.f;
#pragma unroll 8
    for (int j = lane; j < HID; j += 32) {
        float e = ex2f_(xk * tex[j]);
        aD += e;
        aN = fmaf(e, ssh[j], aN);
    }
#pragma unroll
    for (int o = 16; o; o >>= 1) {
        aN += __shfl_xor_sync(0xffffffffu, aN, o);
        aD += __shfl_xor_sync(0xffffffffu, aD, o);
    }
    if (lane == 0) { nodeN[w] = aN; nodeD[w] = aD; }
    __syncthreads();

    if (tid < 32) {
        const int n = tid & 15;
        const float* V = (tid < 16) ? nodeN : nodeD;
        float c = 0.f;
#pragma unroll
        for (int k = 0; k < NNODE; k++)
            c += V[k] * cospif((float)(n * (2 * k + 1)) * (1.0f / 32.0f));
        c *= (n == 0) ? (1.0f / NNODE) : (2.0f / NNODE);
        ((tid < 16) ? cN : cD)[n] = c;
    }
    __syncthreads();

    const float u = (a - m) * rcpf_(h);
    const float u2 = u + u;
    float bN1 = 0.f, bN2 = 0.f, bD1 = 0.f, bD2 = 0.f;
#pragma unroll
    for (int n = NNODE - 1; n >= 1; --n) {
        float tN = fmaf(u2, bN1, cN[n] - bN2);
        float tD = fmaf(u2, bD1, cD[n] - bD2);
        bN2 = bN1; bN1 = tN;
        bD2 = bD1; bD1 = tD;
    }
    float fN = fmaf(u, bN1, cN[0] - bN2);
    float fD = fmaf(u, bD1, cD[0] - bD2);
    float v = fN * rcpf_(fD);
    v = v > 0.f ? v : 0.f;

    unsigned hh, ll;
    split2(v, hh, ll);
    unsigned short* o = Mc + (size_t)b * KE2 + 3 * tid;
    o[0] = (unsigned short)hh; o[1] = (unsigned short)hh; o[2] = (unsigned short)ll;
}

extern "C" void kernel_launch(void* const* d_in, const int* in_sizes, int n_in,
                              void* d_out, int out_size)
{
    const float* combin = (const float*)d_in[0];
    const float* s_emb  = (const float*)d_in[1];
    const float* W1     = (const float*)d_in[2];
    const float* b1     = (const float*)d_in[3];
    const float* W2     = (const float*)d_in[4];
    const float* b2     = (const float*)d_in[5];
    const float* W3     = (const float*)d_in[6];
    const float* b3     = (const float*)d_in[7];
    float* out = (float*)d_out;

    float *A, *T;
    unsigned short *Xc1, *Xc2, *Wc1, *Wc2, *Wc3, *Mc;
    cudaGetSymbolAddress((void**)&A,   g_A);
    cudaGetSymbolAddress((void**)&T,   g_T);
    cudaGetSymbolAddress((void**)&Xc1, g_Xc1);
    cudaGetSymbolAddress((void**)&Xc2, g_Xc2);
    cudaGetSymbolAddress((void**)&Wc1, g_Wc1);
    cudaGetSymbolAddress((void**)&Wc2, g_Wc2);
    cudaGetSymbolAddress((void**)&Wc3, g_Wc3);
    cudaGetSymbolAddress((void**)&Mc,  g_Mc);

    const float sigma = 0.044194173824159216f;  // 1/sqrt(512)

    ConvDesc d0 = { combin, Xc1, BATCH * IN_DIM / 4, 0 };
    ConvDesc d1 = { s_emb,  Xc2, BATCH * HID / 4,    0 };
    ConvDesc d2 = { W2,     Wc1, HID * IN_DIM / 4,   1 };
    ConvDesc d3 = { W1,     Wc2, HID * HID / 4,      1 };
    ConvDesc d4 = { W3,     Wc3, OUT_DIM * HID / 4,  1 };
    // y slices 0-4: splits; 5: A bias prefill; 6: T bias prefill
    convert5<<<dim3(BATCH * IN_DIM / 4 / 256, 7), 256>>>(
        d0, d1, d2, d3, d4, b1, b2, A, T, sigma);

    // GEMM1 + GEMM2, each split-K=2: z = prob*2 + chunk -> 8 x 16 x 4 = 512 CTAs
    gemm_mma<<<dim3(HID / 64, BATCH / 64, 4), 256>>>(
        Xc1, Wc1, A, KE1, sigma,
        Xc2, Wc2, T, KE2, 1.0f, HID, 2);

    attn_cheb<<<BATCH, 512>>>(A, T, s_emb, Mc, b3, out);

    // GEMM3 split-K=6: 4 x 16 x 6 = 384 CTAs, atomic accumulate
    gemm_mma<<<dim3(OUT_DIM / 64, BATCH / 64, 6), 256>>>(
        Mc, Wc3, out, KE2, 1.0f,
        Mc, Wc3, out, KE2, 1.0f, OUT_DIM, 6);
}

// round 13
// speedup vs baseline: 1.7706x; 1.2528x over previous
#include <cuda_runtime.h>
#include <cuda_fp16.h>
#include <math.h>

#define BATCH   1024
#define IN_DIM  768
#define HID     512
#define OUT_DIM 256
#define KE1     (IN_DIM * 2)   // 1536 ext (fp16 2-split)
#define KE2     (HID * 2)      // 1024 ext

// ---- scratch (__device__ globals; allocation-free rule) ----
__device__ float          g_A[2][BATCH * HID];      // split-K partials, c_emb GEMM
__device__ float          g_T[2][BATCH * HID];      // split-K partials, t_emb GEMM
__device__ float          g_O[4][BATCH * OUT_DIM];  // split-K partials, out GEMM
__device__ unsigned short g_Xc1[BATCH * KE1];       // combin split [h,l]
__device__ unsigned short g_Xc2[BATCH * KE2];       // s_emb  split [h,l]
__device__ unsigned short g_Wc1[HID * KE1];         // W2 dup [h,h]
__device__ unsigned short g_Wc2[HID * KE2];         // W1 dup [h,h]
__device__ unsigned short g_Wc3[OUT_DIM * KE2];     // W3 dup [h,h]
__device__ unsigned short g_Mc[BATCH * KE2];        // attn out split [h,l]

#define SIGMA 0.044194173824159216f   // 1/sqrt(512)

__device__ __forceinline__ float ex2f_(float x) {
    float y; asm("ex2.approx.f32 %0, %1;" : "=f"(y) : "f"(x)); return y;
}
__device__ __forceinline__ float rcpf_(float x) {
    float y; asm("rcp.approx.f32 %0, %1;" : "=f"(y) : "f"(x)); return y;
}
// fp16 2-split: h = fp16(v), l = fp16(v - h)   (~21 bits total)
__device__ __forceinline__ void split2h(float v, unsigned &h, unsigned &l) {
    __half hh = __float2half_rn(v);
    float lo = v - __half2float(hh);
    h = (unsigned)__half_as_ushort(hh);
    l = (unsigned)__half_as_ushort(__float2half_rn(lo));
}
__device__ __forceinline__ void ldsm4(unsigned addr, unsigned &r0, unsigned &r1,
                                      unsigned &r2, unsigned &r3) {
    asm volatile("ldmatrix.sync.aligned.m8n8.x4.shared.b16 {%0,%1,%2,%3}, [%4];"
                 : "=r"(r0), "=r"(r1), "=r"(r2), "=r"(r3) : "r"(addr));
}
__device__ __forceinline__ void mma_f16(float c[4], unsigned a0, unsigned a1,
                                        unsigned a2, unsigned a3,
                                        unsigned b0, unsigned b1) {
    asm volatile(
        "mma.sync.aligned.m16n8k16.row.col.f32.f16.f16.f32 "
        "{%0,%1,%2,%3}, {%4,%5,%6,%7}, {%8,%9}, {%0,%1,%2,%3};\n"
        : "+f"(c[0]), "+f"(c[1]), "+f"(c[2]), "+f"(c[3])
        : "r"(a0), "r"(a1), "r"(a2), "r"(a3), "r"(b0), "r"(b1));
}
__device__ __forceinline__ void cpasync16(unsigned s, const void* g) {
    asm volatile("cp.async.cg.shared.global [%0], [%1], 16;" :: "r"(s), "l"(g));
}

// ---------------------------------------------------------------------------
// fp32 -> fp16 conversion: X side 2-split [h,l], W side duplicated [h,h].
// One float4 per thread -> 4 packed words.
// ---------------------------------------------------------------------------
struct ConvDesc { const float* in; unsigned short* out; int quads; int isW; };

__global__ __launch_bounds__(256) void convert5(
    ConvDesc d0, ConvDesc d1, ConvDesc d2, ConvDesc d3, ConvDesc d4)
{
    ConvDesc d;
    switch (blockIdx.y) {
        case 0: d = d0; break; case 1: d = d1; break; case 2: d = d2; break;
        case 3: d = d3; break; default: d = d4; break;
    }
    int q = blockIdx.x * 256 + threadIdx.x;
    if (q >= d.quads) return;
    float4 v = ((const float4*)d.in)[q];
    unsigned h0, l0, h1, l1, h2, l2, h3, l3;
    split2h(v.x, h0, l0); split2h(v.y, h1, l1);
    split2h(v.z, h2, l2); split2h(v.w, h3, l3);
    uint4 o;
    if (d.isW) {
        o.x = h0 | (h0 << 16); o.y = h1 | (h1 << 16);
        o.z = h2 | (h2 << 16); o.w = h3 | (h3 << 16);
    } else {
        o.x = h0 | (l0 << 16); o.y = h1 | (l1 << 16);
        o.z = h2 | (l2 << 16); o.w = h3 | (l3 << 16);
    }
    ((uint4*)d.out)[q] = o;
}

// ---------------------------------------------------------------------------
// fp16 TN GEMM, CTA 64x64, 256 threads (8 warps, 4m x 2n, warp tile 16x32),
// BKext=64, 3-stage single-barrier cp.async pipeline, fragment double-buffer.
// blockIdx.z = prob*splits + sp selects operands and partial output buffer.
// Epilogue: plain fp32 store of the partial (bias added by consumers).
// ---------------------------------------------------------------------------
#define GBK 64
#define ASTG 8192          // one stage: 64 rows * 128B
#define NSTG 3

__global__ __launch_bounds__(256, 3) void gemm_mma(
    const unsigned short* A0, const unsigned short* B0, int Kx0,
    const unsigned short* A1, const unsigned short* B1, int Kx1,
    float* Y0, float* Y1, float* Y2, float* Y3,
    int N, int splits)
{
    __shared__ __align__(16) unsigned char sm[NSTG * ASTG * 2];

    const int z    = blockIdx.z;
    const int prob = z / splits;
    const int sp   = z % splits;
    const unsigned short* A = prob ? A1 : A0;
    const unsigned short* B = prob ? B1 : B0;
    const int Kx = prob ? Kx1 : Kx0;
    float* Y = (z == 0) ? Y0 : (z == 1) ? Y1 : (z == 2) ? Y2 : Y3;
    const int koff = sp * (Kx / splits);
    const int NT   = (Kx / splits) / GBK;

    const int tid  = threadIdx.x;
    const int lane = tid & 31;
    const int wid  = tid >> 5;
    const int bm   = blockIdx.y * 64;
    const int bn   = blockIdx.x * 64;
    const int wm   = (wid & 3) * 16;     // 0,16,32,48
    const int wn   = (wid >> 2) * 32;    // 0,32

    const unsigned smBase = (unsigned)__cvta_generic_to_shared(sm);

    float acc[4][4];
#pragma unroll
    for (int j = 0; j < 4; j++)
#pragma unroll
        for (int r = 0; r < 4; r++) acc[j][r] = 0.f;

    // loader: thread covers granules g0,g0+1 of row lr (A and B each)
    const int lr = tid >> 2;
    const int g0 = (tid & 3) * 2;
    const unsigned short* aG = A + (size_t)(bm + lr) * Kx + koff + g0 * 8;
    const unsigned short* bG = B + (size_t)(bn + lr) * Kx + koff + g0 * 8;
    const unsigned sw0 = (unsigned)(((g0 + 0) ^ (lr & 7)) << 4);
    const unsigned sw1 = (unsigned)(((g0 + 1) ^ (lr & 7)) << 4);
    const unsigned sRowA = smBase + lr * 128;
    const unsigned sRowB = smBase + NSTG * ASTG + lr * 128;

#define LOAD_STAGE(KT, S)                                                     \
    {                                                                         \
        cpasync16(sRowA + (S) * ASTG + sw0, aG + (KT) * GBK + 0);             \
        cpasync16(sRowA + (S) * ASTG + sw1, aG + (KT) * GBK + 8);             \
        cpasync16(sRowB + (S) * ASTG + sw0, bG + (KT) * GBK + 0);             \
        cpasync16(sRowB + (S) * ASTG + sw1, bG + (KT) * GBK + 8);             \
    }

    // ldmatrix per-lane address components
    const int arow = wm + (lane & 15);
    const int akg  = lane >> 4;
    const int brow = wn + (lane & 7) + ((lane >> 4) << 3);
    const int bkg  = (lane >> 3) & 1;
    const unsigned aOff  = (unsigned)(arow * 128);
    const unsigned bOff0 = (unsigned)(brow * 128);
    const unsigned bOff1 = (unsigned)((brow + 16) * 128);
    const int ax = arow & 7;
    const int bx = brow & 7;

    LOAD_STAGE(0, 0); asm volatile("cp.async.commit_group;");
    LOAD_STAGE(1, 1); asm volatile("cp.async.commit_group;");

    unsigned af[2][4], bf0[2][4], bf1[2][4];

#define LDFRAG(KS, BUF, SA, SB)                                               \
    {                                                                         \
        unsigned ga = (unsigned)(((2 * (KS) + akg) ^ ax) << 4);               \
        unsigned gb = (unsigned)(((2 * (KS) + bkg) ^ bx) << 4);               \
        ldsm4((SA) + aOff  + ga, af[BUF][0],  af[BUF][1],  af[BUF][2],  af[BUF][3]);  \
        ldsm4((SB) + bOff0 + gb, bf0[BUF][0], bf0[BUF][1], bf0[BUF][2], bf0[BUF][3]); \
        ldsm4((SB) + bOff1 + gb, bf1[BUF][0], bf1[BUF][1], bf1[BUF][2], bf1[BUF][3]); \
    }
#define DOMMA(BUF)                                                            \
    {                                                                         \
        mma_f16(acc[0], af[BUF][0], af[BUF][1], af[BUF][2], af[BUF][3], bf0[BUF][0], bf0[BUF][1]); \
        mma_f16(acc[1], af[BUF][0], af[BUF][1], af[BUF][2], af[BUF][3], bf0[BUF][2], bf0[BUF][3]); \
        mma_f16(acc[2], af[BUF][0], af[BUF][1], af[BUF][2], af[BUF][3], bf1[BUF][0], bf1[BUF][1]); \
        mma_f16(acc[3], af[BUF][0], af[BUF][1], af[BUF][2], af[BUF][3], bf1[BUF][2], bf1[BUF][3]); \
    }

    for (int kt = 0; kt < NT; kt++) {
        // <=1 younger group pending -> group kt complete
        asm volatile("cp.async.wait_group 1;");
        __syncthreads();
        // refill stage (kt+2)%NSTG: its readers finished in iter kt-1 (barrier)
        if (kt + 2 < NT) LOAD_STAGE(kt + 2, (kt + 2) % NSTG);
        asm volatile("cp.async.commit_group;");

        const unsigned sA = smBase + (kt % NSTG) * ASTG;
        const unsigned sB = smBase + NSTG * ASTG + (kt % NSTG) * ASTG;
        LDFRAG(0, 0, sA, sB);
#pragma unroll
        for (int ks = 0; ks < 4; ks++) {
            if (ks < 3) LDFRAG(ks + 1, (ks + 1) & 1, sA, sB);
            DOMMA(ks & 1);
        }
    }
#undef LOAD_STAGE
#undef LDFRAG
#undef DOMMA

    const int g  = lane >> 2;
    const int c2 = (lane & 3) * 2;
#pragma unroll
    for (int nf = 0; nf < 4; nf++) {
        int col = bn + wn + nf * 8 + c2;
        int r0 = bm + wm + g;
        float2 o0, o1;
        o0.x = acc[nf][0]; o0.y = acc[nf][1];
        o1.x = acc[nf][2]; o1.y = acc[nf][3];
        *(float2*)(Y + (size_t)r0 * N + col)       = o0;
        *(float2*)(Y + (size_t)(r0 + 8) * N + col) = o1;
    }
}

// ---------------------------------------------------------------------------
// Chebyshev attention on split-K partials: a = (A0+A1+b2)*SIGMA,
// t = (T0+T1+b1)*log2e. Writes fp16 2-split rows [h,l] for GEMM3's A operand.
// ---------------------------------------------------------------------------
#define NNODE 16
__global__ __launch_bounds__(512) void attn_cheb(
    const float* __restrict__ A0, const float* __restrict__ A1,
    const float* __restrict__ T0, const float* __restrict__ T1,
    const float* __restrict__ S,
    const float* __restrict__ b1, const float* __restrict__ b2,
    unsigned short* __restrict__ Mc)
{
    __shared__ float tex[HID], ssh[HID];
    __shared__ float rmin[16], rmax[16];
    __shared__ float nodeN[NNODE], nodeD[NNODE];
    __shared__ float cN[NNODE], cD[NNODE];
    __shared__ float mh[2];

    const int b = blockIdx.x;
    const int tid = threadIdx.x;
    const int lane = tid & 31;
    const int w = tid >> 5;
    const size_t idx = (size_t)b * HID + tid;

    tex[tid] = (T0[idx] + T1[idx] + b1[tid]) * 1.44269504088896f;
    ssh[tid] = S[idx];
    float a = (A0[idx] + A1[idx] + b2[tid]) * SIGMA;

    float mn = a, mx = a;
#pragma unroll
    for (int o = 16; o; o >>= 1) {
        mn = fminf(mn, __shfl_xor_sync(0xffffffffu, mn, o));
        mx = fmaxf(mx, __shfl_xor_sync(0xffffffffu, mx, o));
    }
    if (lane == 0) { rmin[w] = mn; rmax[w] = mx; }
    __syncthreads();
    if (tid == 0) {
        float mn2 = rmin[0], mx2 = rmax[0];
#pragma unroll
        for (int i = 1; i < 16; i++) { mn2 = fminf(mn2, rmin[i]); mx2 = fmaxf(mx2, rmax[i]); }
        mh[0] = 0.5f * (mn2 + mx2);
        mh[1] = 0.5f * (mx2 - mn2) + 1e-12f;
    }
    __syncthreads();
    const float m = mh[0], h = mh[1];

    const float xk = fmaf(h, cospif((w + 0.5f) * (1.0f / NNODE)), m);
    float aN = 0.f, aD = 0.f;
#pragma unroll 8
    for (int j = lane; j < HID; j += 32) {
        float e = ex2f_(xk * tex[j]);
        aD += e;
        aN = fmaf(e, ssh[j], aN);
    }
#pragma unroll
    for (int o = 16; o; o >>= 1) {
        aN += __shfl_xor_sync(0xffffffffu, aN, o);
        aD += __shfl_xor_sync(0xffffffffu, aD, o);
    }
    if (lane == 0) { nodeN[w] = aN; nodeD[w] = aD; }
    __syncthreads();

    if (tid < 32) {
        const int n = tid & 15;
        const float* V = (tid < 16) ? nodeN : nodeD;
        float c = 0.f;
#pragma unroll
        for (int k = 0; k < NNODE; k++)
            c += V[k] * cospif((float)(n * (2 * k + 1)) * (1.0f / 32.0f));
        c *= (n == 0) ? (1.0f / NNODE) : (2.0f / NNODE);
        ((tid < 16) ? cN : cD)[n] = c;
    }
    __syncthreads();

    const float u = (a - m) * rcpf_(h);
    const float u2 = u + u;
    float bN1 = 0.f, bN2 = 0.f, bD1 = 0.f, bD2 = 0.f;
#pragma unroll
    for (int n = NNODE - 1; n >= 1; --n) {
        float tN = fmaf(u2, bN1, cN[n] - bN2);
        float tD = fmaf(u2, bD1, cD[n] - bD2);
        bN2 = bN1; bN1 = tN;
        bD2 = bD1; bD1 = tD;
    }
    float fN = fmaf(u, bN1, cN[0] - bN2);
    float fD = fmaf(u, bD1, cD[0] - bD2);
    float v = fN * rcpf_(fD);
    v = v > 0.f ? v : 0.f;

    unsigned hh, ll;
    split2h(v, hh, ll);
    ((unsigned*)(Mc + (size_t)b * KE2))[tid] = hh | (ll << 16);
}

// out = O0 + O1 + O2 + O3 + b3 (float4 per thread)
__global__ __launch_bounds__(256) void sumout(
    const float* __restrict__ P0, const float* __restrict__ P1,
    const float* __restrict__ P2, const float* __restrict__ P3,
    const float* __restrict__ b3, float* __restrict__ out)
{
    int q = blockIdx.x * 256 + threadIdx.x;      // quads over BATCH*OUT_DIM
    float4 p0 = ((const float4*)P0)[q];
    float4 p1 = ((const float4*)P1)[q];
    float4 p2 = ((const float4*)P2)[q];
    float4 p3 = ((const float4*)P3)[q];
    int c = (q * 4) & (OUT_DIM - 1);
    float4 bv = *(const float4*)(b3 + c);
    float4 o;
    o.x = (p0.x + p1.x) + (p2.x + p3.x) + bv.x;
    o.y = (p0.y + p1.y) + (p2.y + p3.y) + bv.y;
    o.z = (p0.z + p1.z) + (p2.z + p3.z) + bv.z;
    o.w = (p0.w + p1.w) + (p2.w + p3.w) + bv.w;
    ((float4*)out)[q] = o;
}

extern "C" void kernel_launch(void* const* d_in, const int* in_sizes, int n_in,
                              void* d_out, int out_size)
{
    const float* combin = (const float*)d_in[0];
    const float* s_emb  = (const float*)d_in[1];
    const float* W1     = (const float*)d_in[2];
    const float* b1     = (const float*)d_in[3];
    const float* W2     = (const float*)d_in[4];
    const float* b2     = (const float*)d_in[5];
    const float* W3     = (const float*)d_in[6];
    const float* b3     = (const float*)d_in[7];
    float* out = (float*)d_out;

    float *A, *T, *O;
    unsigned short *Xc1, *Xc2, *Wc1, *Wc2, *Wc3, *Mc;
    cudaGetSymbolAddress((void**)&A,   g_A);
    cudaGetSymbolAddress((void**)&T,   g_T);
    cudaGetSymbolAddress((void**)&O,   g_O);
    cudaGetSymbolAddress((void**)&Xc1, g_Xc1);
    cudaGetSymbolAddress((void**)&Xc2, g_Xc2);
    cudaGetSymbolAddress((void**)&Wc1, g_Wc1);
    cudaGetSymbolAddress((void**)&Wc2, g_Wc2);
    cudaGetSymbolAddress((void**)&Wc3, g_Wc3);
    cudaGetSymbolAddress((void**)&Mc,  g_Mc);
    float* A1p = A + BATCH * HID;
    float* T1p = T + BATCH * HID;
    float* O1p = O + 1 * BATCH * OUT_DIM;
    float* O2p = O + 2 * BATCH * OUT_DIM;
    float* O3p = O + 3 * BATCH * OUT_DIM;

    ConvDesc d0 = { combin, Xc1, BATCH * IN_DIM / 4, 0 };
    ConvDesc d1 = { s_emb,  Xc2, BATCH * HID / 4,    0 };
    ConvDesc d2 = { W2,     Wc1, HID * IN_DIM / 4,   1 };
    ConvDesc d3 = { W1,     Wc2, HID * HID / 4,      1 };
    ConvDesc d4 = { W3,     Wc3, OUT_DIM * HID / 4,  1 };
    convert5<<<dim3(BATCH * IN_DIM / 4 / 256, 5), 256>>>(d0, d1, d2, d3, d4);

    // GEMM1 + GEMM2, each split-K=2: z = prob*2 + sp -> 8 x 16 x 4 = 512 CTAs
    // partials: z0->A[0], z1->A[1], z2->T[0], z3->T[1]
    gemm_mma<<<dim3(HID / 64, BATCH / 64, 4), 256>>>(
        Xc1, Wc1, KE1, Xc2, Wc2, KE2,
        A, A1p, T, T1p, HID, 2);

    attn_cheb<<<BATCH, 512>>>(A, A1p, T, T1p, s_emb, b1, b2, Mc);

    // GEMM3 split-K=4: 4 x 16 x 4 = 256 CTAs, NT=4 each, partials O0..O3
    gemm_mma<<<dim3(OUT_DIM / 64, BATCH / 64, 4), 256>>>(
        Mc, Wc3, KE2, Mc, Wc3, KE2,
        O, O1p, O2p, O3p, OUT_DIM, 4);

    sumout<<<BATCH * OUT_DIM / 4 / 256, 256>>>(O, O1p, O2p, O3p, b3, out);
}

// round 14
// speedup vs baseline: 2.2459x; 1.2684x over previous
#include <cuda_runtime.h>
#include <cuda_fp16.h>
#include <math.h>

#define BATCH   1024
#define IN_DIM  768
#define HID     512
#define OUT_DIM 256

// ---- scratch (__device__ globals; allocation-free rule) ----
__device__ float          g_A[BATCH * HID];         // (combin@W2^T + b2)*SIGMA
__device__ float          g_T[BATCH * HID];         // s_emb@W1^T + b1
__device__ float          g_O[2][BATCH * OUT_DIM];  // GEMM3 split-K partials
__device__ unsigned short g_Xc1[BATCH * IN_DIM];    // combin fp16
__device__ unsigned short g_Xc2[BATCH * HID];       // s_emb fp16
__device__ unsigned short g_Wc1[HID * IN_DIM];      // W2 fp16
__device__ unsigned short g_Wc2[HID * HID];         // W1 fp16
__device__ unsigned short g_Wc3[OUT_DIM * HID];     // W3 fp16
__device__ unsigned short g_Mc[BATCH * HID];        // attn out fp16

#define SIGMA 0.044194173824159216f   // 1/sqrt(512)

__device__ __forceinline__ float ex2f_(float x) {
    float y; asm("ex2.approx.f32 %0, %1;" : "=f"(y) : "f"(x)); return y;
}
__device__ __forceinline__ float rcpf_(float x) {
    float y; asm("rcp.approx.f32 %0, %1;" : "=f"(y) : "f"(x)); return y;
}
__device__ __forceinline__ void ldsm4(unsigned addr, unsigned &r0, unsigned &r1,
                                      unsigned &r2, unsigned &r3) {
    asm volatile("ldmatrix.sync.aligned.m8n8.x4.shared.b16 {%0,%1,%2,%3}, [%4];"
                 : "=r"(r0), "=r"(r1), "=r"(r2), "=r"(r3) : "r"(addr));
}
__device__ __forceinline__ void mma_f16(float c[4], unsigned a0, unsigned a1,
                                        unsigned a2, unsigned a3,
                                        unsigned b0, unsigned b1) {
    asm volatile(
        "mma.sync.aligned.m16n8k16.row.col.f32.f16.f16.f32 "
        "{%0,%1,%2,%3}, {%4,%5,%6,%7}, {%8,%9}, {%0,%1,%2,%3};\n"
        : "+f"(c[0]), "+f"(c[1]), "+f"(c[2]), "+f"(c[3])
        : "r"(a0), "r"(a1), "r"(a2), "r"(a3), "r"(b0), "r"(b1));
}
__device__ __forceinline__ void cpasync16(unsigned s, const void* g) {
    asm volatile("cp.async.cg.shared.global [%0], [%1], 16;" :: "r"(s), "l"(g));
}

// ---------------------------------------------------------------------------
// fp32 -> fp16 conversion, one float4 -> uint2 (4 halves) per thread.
// ---------------------------------------------------------------------------
struct ConvDesc { const float* in; unsigned short* out; int quads; };

__global__ __launch_bounds__(256) void convert5(
    ConvDesc d0, ConvDesc d1, ConvDesc d2, ConvDesc d3, ConvDesc d4)
{
    ConvDesc d;
    switch (blockIdx.y) {
        case 0: d = d0; break; case 1: d = d1; break; case 2: d = d2; break;
        case 3: d = d3; break; default: d = d4; break;
    }
    int q = blockIdx.x * 256 + threadIdx.x;
    if (q >= d.quads) return;
    float4 v = ((const float4*)d.in)[q];
    unsigned h0 = (unsigned)__half_as_ushort(__float2half_rn(v.x));
    unsigned h1 = (unsigned)__half_as_ushort(__float2half_rn(v.y));
    unsigned h2 = (unsigned)__half_as_ushort(__float2half_rn(v.z));
    unsigned h3 = (unsigned)__half_as_ushort(__float2half_rn(v.w));
    uint2 o;
    o.x = h0 | (h1 << 16);
    o.y = h2 | (h3 << 16);
    ((uint2*)d.out)[q] = o;
}

// ---------------------------------------------------------------------------
// fp16 TN GEMM, CTA 64x64, 256 threads (8 warps, 4m x 2n, warp tile 16x32),
// BK=64, 3-stage single-barrier cp.async pipeline, fragment double-buffer.
// splits==1: z = problem; epilogue (acc + bias)*osc direct store.
// splits==2: z = K-chunk; plain partial store (bias added by sumout).
// ---------------------------------------------------------------------------
#define GBK 64
#define ASTG 8192          // one stage: 64 rows * 128B
#define NSTG 3

__global__ __launch_bounds__(256, 3) void gemm_mma(
    const unsigned short* A0, const unsigned short* B0,
    const float* bias0, float* Y0, int Kx0, float osc0,
    const unsigned short* A1, const unsigned short* B1,
    const float* bias1, float* Y1, int Kx1, float osc1,
    int N, int splits)
{
    __shared__ __align__(16) unsigned char sm[NSTG * ASTG * 2];

    const int z    = blockIdx.z;
    const int prob = z / splits;
    const int sp   = z % splits;
    const unsigned short* A = prob ? A1 : A0;
    const unsigned short* B = prob ? B1 : B0;
    const float* bias = prob ? bias1 : bias0;
    const float osc   = prob ? osc1 : osc0;
    float* Y = z ? Y1 : Y0;
    const int Kx   = prob ? Kx1 : Kx0;
    const int koff = sp * (Kx / splits);
    const int NT   = (Kx / splits) / GBK;

    const int tid  = threadIdx.x;
    const int lane = tid & 31;
    const int wid  = tid >> 5;
    const int bm   = blockIdx.y * 64;
    const int bn   = blockIdx.x * 64;
    const int wm   = (wid & 3) * 16;     // 0,16,32,48
    const int wn   = (wid >> 2) * 32;    // 0,32

    const unsigned smBase = (unsigned)__cvta_generic_to_shared(sm);

    float acc[4][4];
#pragma unroll
    for (int j = 0; j < 4; j++)
#pragma unroll
        for (int r = 0; r < 4; r++) acc[j][r] = 0.f;

    // loader: thread covers granules g0,g0+1 of row lr (A and B each)
    const int lr = tid >> 2;
    const int g0 = (tid & 3) * 2;
    const unsigned short* aG = A + (size_t)(bm + lr) * Kx + koff + g0 * 8;
    const unsigned short* bG = B + (size_t)(bn + lr) * Kx + koff + g0 * 8;
    const unsigned sw0 = (unsigned)(((g0 + 0) ^ (lr & 7)) << 4);
    const unsigned sw1 = (unsigned)(((g0 + 1) ^ (lr & 7)) << 4);
    const unsigned sRowA = smBase + lr * 128;
    const unsigned sRowB = smBase + NSTG * ASTG + lr * 128;

#define LOAD_STAGE(KT, S)                                                     \
    {                                                                         \
        cpasync16(sRowA + (S) * ASTG + sw0, aG + (KT) * GBK + 0);             \
        cpasync16(sRowA + (S) * ASTG + sw1, aG + (KT) * GBK + 8);             \
        cpasync16(sRowB + (S) * ASTG + sw0, bG + (KT) * GBK + 0);             \
        cpasync16(sRowB + (S) * ASTG + sw1, bG + (KT) * GBK + 8);             \
    }

    // ldmatrix per-lane address components
    const int arow = wm + (lane & 15);
    const int akg  = lane >> 4;
    const int brow = wn + (lane & 7) + ((lane >> 4) << 3);
    const int bkg  = (lane >> 3) & 1;
    const unsigned aOff  = (unsigned)(arow * 128);
    const unsigned bOff0 = (unsigned)(brow * 128);
    const unsigned bOff1 = (unsigned)((brow + 16) * 128);
    const int ax = arow & 7;
    const int bx = brow & 7;

    LOAD_STAGE(0, 0); asm volatile("cp.async.commit_group;");
    LOAD_STAGE(1, 1); asm volatile("cp.async.commit_group;");

    unsigned af[2][4], bf0[2][4], bf1[2][4];

#define LDFRAG(KS, BUF, SA, SB)                                               \
    {                                                                         \
        unsigned ga = (unsigned)(((2 * (KS) + akg) ^ ax) << 4);               \
        unsigned gb = (unsigned)(((2 * (KS) + bkg) ^ bx) << 4);               \
        ldsm4((SA) + aOff  + ga, af[BUF][0],  af[BUF][1],  af[BUF][2],  af[BUF][3]);  \
        ldsm4((SB) + bOff0 + gb, bf0[BUF][0], bf0[BUF][1], bf0[BUF][2], bf0[BUF][3]); \
        ldsm4((SB) + bOff1 + gb, bf1[BUF][0], bf1[BUF][1], bf1[BUF][2], bf1[BUF][3]); \
    }
#define DOMMA(BUF)                                                            \
    {                                                                         \
        mma_f16(acc[0], af[BUF][0], af[BUF][1], af[BUF][2], af[BUF][3], bf0[BUF][0], bf0[BUF][1]); \
        mma_f16(acc[1], af[BUF][0], af[BUF][1], af[BUF][2], af[BUF][3], bf0[BUF][2], bf0[BUF][3]); \
        mma_f16(acc[2], af[BUF][0], af[BUF][1], af[BUF][2], af[BUF][3], bf1[BUF][0], bf1[BUF][1]); \
        mma_f16(acc[3], af[BUF][0], af[BUF][1], af[BUF][2], af[BUF][3], bf1[BUF][2], bf1[BUF][3]); \
    }

    for (int kt = 0; kt < NT; kt++) {
        // <=1 younger group pending -> group kt complete
        asm volatile("cp.async.wait_group 1;");
        __syncthreads();
        // refill stage (kt+2)%NSTG: readers finished in iter kt-1 (barrier)
        if (kt + 2 < NT) LOAD_STAGE(kt + 2, (kt + 2) % NSTG);
        asm volatile("cp.async.commit_group;");

        const unsigned sA = smBase + (kt % NSTG) * ASTG;
        const unsigned sB = smBase + NSTG * ASTG + (kt % NSTG) * ASTG;
        LDFRAG(0, 0, sA, sB);
#pragma unroll
        for (int ks = 0; ks < 4; ks++) {
            if (ks < 3) LDFRAG(ks + 1, (ks + 1) & 1, sA, sB);
            DOMMA(ks & 1);
        }
    }
#undef LOAD_STAGE
#undef LDFRAG
#undef DOMMA

    const int g  = lane >> 2;
    const int c2 = (lane & 3) * 2;
    if (splits == 1) {
#pragma unroll
        for (int nf = 0; nf < 4; nf++) {
            int col = bn + wn + nf * 8 + c2;
            float2 bv = *(const float2*)(bias + col);
            int r0 = bm + wm + g;
            float2 o0, o1;
            o0.x = (acc[nf][0] + bv.x) * osc;
            o0.y = (acc[nf][1] + bv.y) * osc;
            o1.x = (acc[nf][2] + bv.x) * osc;
            o1.y = (acc[nf][3] + bv.y) * osc;
            *(float2*)(Y + (size_t)r0 * N + col)       = o0;
            *(float2*)(Y + (size_t)(r0 + 8) * N + col) = o1;
        }
    } else {
#pragma unroll
        for (int nf = 0; nf < 4; nf++) {
            int col = bn + wn + nf * 8 + c2;
            int r0 = bm + wm + g;
            float2 o0, o1;
            o0.x = acc[nf][0]; o0.y = acc[nf][1];
            o1.x = acc[nf][2]; o1.y = acc[nf][3];
            *(float2*)(Y + (size_t)r0 * N + col)       = o0;
            *(float2*)(Y + (size_t)(r0 + 8) * N + col) = o1;
        }
    }
}

// ---------------------------------------------------------------------------
// Chebyshev attention: a = A[idx] (pre-scaled), t = T[idx]*log2e.
// out_i = relu(f(a_i)), f(a) = sum_j s_j 2^(a t_j) / sum_j 2^(a t_j),
// via 16-node Chebyshev interpolation of N(a), D(a). Writes fp16 Mc.
// ---------------------------------------------------------------------------
#define NNODE 16
__global__ __launch_bounds__(512) void attn_cheb(
    const float* __restrict__ A, const float* __restrict__ T,
    const float* __restrict__ S, unsigned short* __restrict__ Mc)
{
    __shared__ float tex[HID], ssh[HID];
    __shared__ float rmin[16], rmax[16];
    __shared__ float nodeN[NNODE], nodeD[NNODE];
    __shared__ float cN[NNODE], cD[NNODE];
    __shared__ float mh[2];

    const int b = blockIdx.x;
    const int tid = threadIdx.x;
    const int lane = tid & 31;
    const int w = tid >> 5;
    const size_t idx = (size_t)b * HID + tid;

    tex[tid] = T[idx] * 1.44269504088896f;
    ssh[tid] = S[idx];
    float a = A[idx];

    float mn = a, mx = a;
#pragma unroll
    for (int o = 16; o; o >>= 1) {
        mn = fminf(mn, __shfl_xor_sync(0xffffffffu, mn, o));
        mx = fmaxf(mx, __shfl_xor_sync(0xffffffffu, mx, o));
    }
    if (lane == 0) { rmin[w] = mn; rmax[w] = mx; }
    __syncthreads();
    if (tid == 0) {
        float mn2 = rmin[0], mx2 = rmax[0];
#pragma unroll
        for (int i = 1; i < 16; i++) { mn2 = fminf(mn2, rmin[i]); mx2 = fmaxf(mx2, rmax[i]); }
        mh[0] = 0.5f * (mn2 + mx2);
        mh[1] = 0.5f * (mx2 - mn2) + 1e-12f;
    }
    __syncthreads();
    const float m = mh[0], h = mh[1];

    const float xk = fmaf(h, cospif((w + 0.5f) * (1.0f / NNODE)), m);
    float aN = 0.f, aD = 0.f;
#pragma unroll 8
    for (int j = lane; j < HID; j += 32) {
        float e = ex2f_(xk * tex[j]);
        aD += e;
        aN = fmaf(e, ssh[j], aN);
    }
#pragma unroll
    for (int o = 16; o; o >>= 1) {
        aN += __shfl_xor_sync(0xffffffffu, aN, o);
        aD += __shfl_xor_sync(0xffffffffu, aD, o);
    }
    if (lane == 0) { nodeN[w] = aN; nodeD[w] = aD; }
    __syncthreads();

    if (tid < 32) {
        const int n = tid & 15;
        const float* V = (tid < 16) ? nodeN : nodeD;
        float c = 0.f;
#pragma unroll
        for (int k = 0; k < NNODE; k++)
            c += V[k] * cospif((float)(n * (2 * k + 1)) * (1.0f / 32.0f));
        c *= (n == 0) ? (1.0f / NNODE) : (2.0f / NNODE);
        ((tid < 16) ? cN : cD)[n] = c;
    }
    __syncthreads();

    const float u = (a - m) * rcpf_(h);
    const float u2 = u + u;
    float bN1 = 0.f, bN2 = 0.f, bD1 = 0.f, bD2 = 0.f;
#pragma unroll
    for (int n = NNODE - 1; n >= 1; --n) {
        float tN = fmaf(u2, bN1, cN[n] - bN2);
        float tD = fmaf(u2, bD1, cD[n] - bD2);
        bN2 = bN1; bN1 = tN;
        bD2 = bD1; bD1 = tD;
    }
    float fN = fmaf(u, bN1, cN[0] - bN2);
    float fD = fmaf(u, bD1, cD[0] - bD2);
    float v = fN * rcpf_(fD);
    v = v > 0.f ? v : 0.f;

    Mc[idx] = __half_as_ushort(__float2half_rn(v));
}

// out = O0 + O1 + b3 (float4 per thread)
__global__ __launch_bounds__(256) void sumout(
    const float* __restrict__ P0, const float* __restrict__ P1,
    const float* __restrict__ b3, float* __restrict__ out)
{
    int q = blockIdx.x * 256 + threadIdx.x;      // quads over BATCH*OUT_DIM
    float4 p0 = ((const float4*)P0)[q];
    float4 p1 = ((const float4*)P1)[q];
    int c = (q * 4) & (OUT_DIM - 1);
    float4 bv = *(const float4*)(b3 + c);
    float4 o;
    o.x = p0.x + p1.x + bv.x;
    o.y = p0.y + p1.y + bv.y;
    o.z = p0.z + p1.z + bv.z;
    o.w = p0.w + p1.w + bv.w;
    ((float4*)out)[q] = o;
}

extern "C" void kernel_launch(void* const* d_in, const int* in_sizes, int n_in,
                              void* d_out, int out_size)
{
    const float* combin = (const float*)d_in[0];
    const float* s_emb  = (const float*)d_in[1];
    const float* W1     = (const float*)d_in[2];
    const float* b1     = (const float*)d_in[3];
    const float* W2     = (const float*)d_in[4];
    const float* b2     = (const float*)d_in[5];
    const float* W3     = (const float*)d_in[6];
    const float* b3     = (const float*)d_in[7];
    float* out = (float*)d_out;

    float *A, *T, *O;
    unsigned short *Xc1, *Xc2, *Wc1, *Wc2, *Wc3, *Mc;
    cudaGetSymbolAddress((void**)&A,   g_A);
    cudaGetSymbolAddress((void**)&T,   g_T);
    cudaGetSymbolAddress((void**)&O,   g_O);
    cudaGetSymbolAddress((void**)&Xc1, g_Xc1);
    cudaGetSymbolAddress((void**)&Xc2, g_Xc2);
    cudaGetSymbolAddress((void**)&Wc1, g_Wc1);
    cudaGetSymbolAddress((void**)&Wc2, g_Wc2);
    cudaGetSymbolAddress((void**)&Wc3, g_Wc3);
    cudaGetSymbolAddress((void**)&Mc,  g_Mc);
    float* O1p = O + BATCH * OUT_DIM;

    ConvDesc d0 = { combin, Xc1, BATCH * IN_DIM / 4 };
    ConvDesc d1 = { s_emb,  Xc2, BATCH * HID / 4 };
    ConvDesc d2 = { W2,     Wc1, HID * IN_DIM / 4 };
    ConvDesc d3 = { W1,     Wc2, HID * HID / 4 };
    ConvDesc d4 = { W3,     Wc3, OUT_DIM * HID / 4 };
    convert5<<<dim3(BATCH * IN_DIM / 4 / 256, 5), 256>>>(d0, d1, d2, d3, d4);

    // GEMM1 + GEMM2 (splits=1, z=prob): 8 x 16 x 2 = 256 CTAs
    // A = (combin@W2^T + b2)*SIGMA ; T = s_emb@W1^T + b1
    gemm_mma<<<dim3(HID / 64, BATCH / 64, 2), 256>>>(
        Xc1, Wc1, b2, A, IN_DIM, SIGMA,
        Xc2, Wc2, b1, T, HID,    1.0f, HID, 1);

    attn_cheb<<<BATCH, 512>>>(A, T, s_emb, Mc);

    // GEMM3 split-K=2 (z = chunk): 4 x 16 x 2 = 128 CTAs, partials O0/O1
    gemm_mma<<<dim3(OUT_DIM / 64, BATCH / 64, 2), 256>>>(
        Mc, Wc3, b3, O, HID, 1.0f,
        Mc, Wc3, b3, O1p, HID, 1.0f, OUT_DIM, 2);

    sumout<<<BATCH * OUT_DIM / 4 / 256, 256>>>(O, O1p, b3, out);
}

// round 15
// speedup vs baseline: 2.4061x; 1.0714x over previous
#include <cuda_runtime.h>
#include <cuda_fp16.h>
#include <math.h>

#define BATCH   1024
#define IN_DIM  768
#define HID     512
#define OUT_DIM 256

// ---- scratch (__device__ globals; allocation-free rule) ----
__device__ float          g_A[2][BATCH * HID];      // GEMM1 split-K partials
__device__ float          g_T[2][BATCH * HID];      // GEMM2 split-K partials
__device__ unsigned short g_Xc1[BATCH * IN_DIM];    // combin fp16
__device__ unsigned short g_Xc2[BATCH * HID];       // s_emb fp16
__device__ unsigned short g_Wc1[HID * IN_DIM];      // W2 fp16
__device__ unsigned short g_Wc2[HID * HID];         // W1 fp16
__device__ unsigned short g_Wc3[OUT_DIM * HID];     // W3 fp16
__device__ unsigned short g_Mc[BATCH * HID];        // attn out fp16

#define SIGMA 0.044194173824159216f   // 1/sqrt(512)

__device__ __forceinline__ float ex2f_(float x) {
    float y; asm("ex2.approx.f32 %0, %1;" : "=f"(y) : "f"(x)); return y;
}
__device__ __forceinline__ float rcpf_(float x) {
    float y; asm("rcp.approx.f32 %0, %1;" : "=f"(y) : "f"(x)); return y;
}
__device__ __forceinline__ void ldsm4(unsigned addr, unsigned &r0, unsigned &r1,
                                      unsigned &r2, unsigned &r3) {
    asm volatile("ldmatrix.sync.aligned.m8n8.x4.shared.b16 {%0,%1,%2,%3}, [%4];"
                 : "=r"(r0), "=r"(r1), "=r"(r2), "=r"(r3) : "r"(addr));
}
__device__ __forceinline__ void mma_f16(float c[4], unsigned a0, unsigned a1,
                                        unsigned a2, unsigned a3,
                                        unsigned b0, unsigned b1) {
    asm volatile(
        "mma.sync.aligned.m16n8k16.row.col.f32.f16.f16.f32 "
        "{%0,%1,%2,%3}, {%4,%5,%6,%7}, {%8,%9}, {%0,%1,%2,%3};\n"
        : "+f"(c[0]), "+f"(c[1]), "+f"(c[2]), "+f"(c[3])
        : "r"(a0), "r"(a1), "r"(a2), "r"(a3), "r"(b0), "r"(b1));
}
__device__ __forceinline__ void cpasync16(unsigned s, const void* g) {
    asm volatile("cp.async.cg.shared.global [%0], [%1], 16;" :: "r"(s), "l"(g));
}

// ---------------------------------------------------------------------------
// fp32 -> fp16 conversion, one float4 -> uint2 (4 halves) per thread.
// ---------------------------------------------------------------------------
struct ConvDesc { const float* in; unsigned short* out; int quads; };

__global__ __launch_bounds__(256) void convert5(
    ConvDesc d0, ConvDesc d1, ConvDesc d2, ConvDesc d3, ConvDesc d4)
{
    ConvDesc d;
    switch (blockIdx.y) {
        case 0: d = d0; break; case 1: d = d1; break; case 2: d = d2; break;
        case 3: d = d3; break; default: d = d4; break;
    }
    int q = blockIdx.x * 256 + threadIdx.x;
    if (q >= d.quads) return;
    float4 v = ((const float4*)d.in)[q];
    unsigned h0 = (unsigned)__half_as_ushort(__float2half_rn(v.x));
    unsigned h1 = (unsigned)__half_as_ushort(__float2half_rn(v.y));
    unsigned h2 = (unsigned)__half_as_ushort(__float2half_rn(v.z));
    unsigned h3 = (unsigned)__half_as_ushort(__float2half_rn(v.w));
    uint2 o;
    o.x = h0 | (h1 << 16);
    o.y = h2 | (h3 << 16);
    ((uint2*)d.out)[q] = o;
}

// ---------------------------------------------------------------------------
// fp16 TN GEMM, CTA 64x64, 256 threads (8 warps, 4m x 2n, warp tile 16x32),
// BK=64, 3-stage single-barrier cp.async pipeline, fragment double-buffer.
// z = prob*splits + k-chunk; Y picked by z (partial buffers or shared target).
// epi: 1 = plain partial store, 2 = atomicAdd into Y (bias pre-filled).
// ---------------------------------------------------------------------------
#define GBK 64
#define ASTG 8192          // one stage: 64 rows * 128B
#define NSTG 3

__global__ __launch_bounds__(256, 3) void gemm_mma(
    const unsigned short* A0, const unsigned short* B0, int Kx0,
    const unsigned short* A1, const unsigned short* B1, int Kx1,
    float* Y0, float* Y1, float* Y2, float* Y3,
    int N, int splits, int epi)
{
    __shared__ __align__(16) unsigned char sm[NSTG * ASTG * 2];

    const int z    = blockIdx.z;
    const int prob = z / splits;
    const int sp   = z % splits;
    const unsigned short* A = prob ? A1 : A0;
    const unsigned short* B = prob ? B1 : B0;
    float* Y = (z == 0) ? Y0 : (z == 1) ? Y1 : (z == 2) ? Y2 : Y3;
    const int Kx   = prob ? Kx1 : Kx0;
    const int koff = sp * (Kx / splits);
    const int NT   = (Kx / splits) / GBK;

    const int tid  = threadIdx.x;
    const int lane = tid & 31;
    const int wid  = tid >> 5;
    const int bm   = blockIdx.y * 64;
    const int bn   = blockIdx.x * 64;
    const int wm   = (wid & 3) * 16;     // 0,16,32,48
    const int wn   = (wid >> 2) * 32;    // 0,32

    const unsigned smBase = (unsigned)__cvta_generic_to_shared(sm);

    float acc[4][4];
#pragma unroll
    for (int j = 0; j < 4; j++)
#pragma unroll
        for (int r = 0; r < 4; r++) acc[j][r] = 0.f;

    // loader: thread covers granules g0,g0+1 of row lr (A and B each)
    const int lr = tid >> 2;
    const int g0 = (tid & 3) * 2;
    const unsigned short* aG = A + (size_t)(bm + lr) * Kx + koff + g0 * 8;
    const unsigned short* bG = B + (size_t)(bn + lr) * Kx + koff + g0 * 8;
    const unsigned sw0 = (unsigned)(((g0 + 0) ^ (lr & 7)) << 4);
    const unsigned sw1 = (unsigned)(((g0 + 1) ^ (lr & 7)) << 4);
    const unsigned sRowA = smBase + lr * 128;
    const unsigned sRowB = smBase + NSTG * ASTG + lr * 128;

#define LOAD_STAGE(KT, S)                                                     \
    {                                                                         \
        cpasync16(sRowA + (S) * ASTG + sw0, aG + (KT) * GBK + 0);             \
        cpasync16(sRowA + (S) * ASTG + sw1, aG + (KT) * GBK + 8);             \
        cpasync16(sRowB + (S) * ASTG + sw0, bG + (KT) * GBK + 0);             \
        cpasync16(sRowB + (S) * ASTG + sw1, bG + (KT) * GBK + 8);             \
    }

    // ldmatrix per-lane address components
    const int arow = wm + (lane & 15);
    const int akg  = lane >> 4;
    const int brow = wn + (lane & 7) + ((lane >> 4) << 3);
    const int bkg  = (lane >> 3) & 1;
    const unsigned aOff  = (unsigned)(arow * 128);
    const unsigned bOff0 = (unsigned)(brow * 128);
    const unsigned bOff1 = (unsigned)((brow + 16) * 128);
    const int ax = arow & 7;
    const int bx = brow & 7;

    LOAD_STAGE(0, 0); asm volatile("cp.async.commit_group;");
    LOAD_STAGE(1, 1); asm volatile("cp.async.commit_group;");

    unsigned af[2][4], bf0[2][4], bf1[2][4];

#define LDFRAG(KS, BUF, SA, SB)                                               \
    {                                                                         \
        unsigned ga = (unsigned)(((2 * (KS) + akg) ^ ax) << 4);               \
        unsigned gb = (unsigned)(((2 * (KS) + bkg) ^ bx) << 4);               \
        ldsm4((SA) + aOff  + ga, af[BUF][0],  af[BUF][1],  af[BUF][2],  af[BUF][3]);  \
        ldsm4((SB) + bOff0 + gb, bf0[BUF][0], bf0[BUF][1], bf0[BUF][2], bf0[BUF][3]); \
        ldsm4((SB) + bOff1 + gb, bf1[BUF][0], bf1[BUF][1], bf1[BUF][2], bf1[BUF][3]); \
    }
#define DOMMA(BUF)                                                            \
    {                                                                         \
        mma_f16(acc[0], af[BUF][0], af[BUF][1], af[BUF][2], af[BUF][3], bf0[BUF][0], bf0[BUF][1]); \
        mma_f16(acc[1], af[BUF][0], af[BUF][1], af[BUF][2], af[BUF][3], bf0[BUF][2], bf0[BUF][3]); \
        mma_f16(acc[2], af[BUF][0], af[BUF][1], af[BUF][2], af[BUF][3], bf1[BUF][0], bf1[BUF][1]); \
        mma_f16(acc[3], af[BUF][0], af[BUF][1], af[BUF][2], af[BUF][3], bf1[BUF][2], bf1[BUF][3]); \
    }

    for (int kt = 0; kt < NT; kt++) {
        // <=1 younger group pending -> group kt complete
        asm volatile("cp.async.wait_group 1;");
        __syncthreads();
        // refill stage (kt+2)%NSTG: readers finished in iter kt-1 (barrier)
        if (kt + 2 < NT) LOAD_STAGE(kt + 2, (kt + 2) % NSTG);
        asm volatile("cp.async.commit_group;");

        const unsigned sA = smBase + (kt % NSTG) * ASTG;
        const unsigned sB = smBase + NSTG * ASTG + (kt % NSTG) * ASTG;
        LDFRAG(0, 0, sA, sB);
#pragma unroll
        for (int ks = 0; ks < 4; ks++) {
            if (ks < 3) LDFRAG(ks + 1, (ks + 1) & 1, sA, sB);
            DOMMA(ks & 1);
        }
    }
#undef LOAD_STAGE
#undef LDFRAG
#undef DOMMA

    const int g  = lane >> 2;
    const int c2 = (lane & 3) * 2;
    if (epi == 1) {
#pragma unroll
        for (int nf = 0; nf < 4; nf++) {
            int col = bn + wn + nf * 8 + c2;
            int r0 = bm + wm + g;
            float2 o0, o1;
            o0.x = acc[nf][0]; o0.y = acc[nf][1];
            o1.x = acc[nf][2]; o1.y = acc[nf][3];
            *(float2*)(Y + (size_t)r0 * N + col)       = o0;
            *(float2*)(Y + (size_t)(r0 + 8) * N + col) = o1;
        }
    } else {
#pragma unroll
        for (int nf = 0; nf < 4; nf++) {
            int col = bn + wn + nf * 8 + c2;
            int r0 = bm + wm + g;
            atomicAdd(Y + (size_t)r0 * N + col,           acc[nf][0]);
            atomicAdd(Y + (size_t)r0 * N + col + 1,       acc[nf][1]);
            atomicAdd(Y + (size_t)(r0 + 8) * N + col,     acc[nf][2]);
            atomicAdd(Y + (size_t)(r0 + 8) * N + col + 1, acc[nf][3]);
        }
    }
}

// ---------------------------------------------------------------------------
// Chebyshev attention on split-K partials: a = (A0+A1+b2)*SIGMA,
// t = (T0+T1+b1)*log2e. Writes fp16 Mc for GEMM3's A operand and pre-fills
// the output matrix with bias b3 (GEMM3 accumulates atomically on top).
// ---------------------------------------------------------------------------
#define NNODE 16
__global__ __launch_bounds__(512) void attn_cheb(
    const float* __restrict__ A0, const float* __restrict__ A1,
    const float* __restrict__ T0, const float* __restrict__ T1,
    const float* __restrict__ S,
    const float* __restrict__ b1, const float* __restrict__ b2,
    unsigned short* __restrict__ Mc,
    const float* __restrict__ b3, float* __restrict__ out)
{
    __shared__ float tex[HID], ssh[HID];
    __shared__ float rmin[16], rmax[16];
    __shared__ float nodeN[NNODE], nodeD[NNODE];
    __shared__ float cN[NNODE], cD[NNODE];
    __shared__ float mh[2];

    const int b = blockIdx.x;
    const int tid = threadIdx.x;
    const int lane = tid & 31;
    const int w = tid >> 5;
    const size_t idx = (size_t)b * HID + tid;

    if (tid < OUT_DIM) out[(size_t)b * OUT_DIM + tid] = b3[tid];

    tex[tid] = (T0[idx] + T1[idx] + b1[tid]) * 1.44269504088896f;
    ssh[tid] = S[idx];
    float a = (A0[idx] + A1[idx] + b2[tid]) * SIGMA;

    float mn = a, mx = a;
#pragma unroll
    for (int o = 16; o; o >>= 1) {
        mn = fminf(mn, __shfl_xor_sync(0xffffffffu, mn, o));
        mx = fmaxf(mx, __shfl_xor_sync(0xffffffffu, mx, o));
    }
    if (lane == 0) { rmin[w] = mn; rmax[w] = mx; }
    __syncthreads();
    if (tid == 0) {
        float mn2 = rmin[0], mx2 = rmax[0];
#pragma unroll
        for (int i = 1; i < 16; i++) { mn2 = fminf(mn2, rmin[i]); mx2 = fmaxf(mx2, rmax[i]); }
        mh[0] = 0.5f * (mn2 + mx2);
        mh[1] = 0.5f * (mx2 - mn2) + 1e-12f;
    }
    __syncthreads();
    const float m = mh[0], h = mh[1];

    const float xk = fmaf(h, cospif((w + 0.5f) * (1.0f / NNODE)), m);
    float aN = 0.f, aD = 0.f;
#pragma unroll 8
    for (int j = lane; j < HID; j += 32) {
        float e = ex2f_(xk * tex[j]);
        aD += e;
        aN = fmaf(e, ssh[j], aN);
    }
#pragma unroll
    for (int o = 16; o; o >>= 1) {
        aN += __shfl_xor_sync(0xffffffffu, aN, o);
        aD += __shfl_xor_sync(0xffffffffu, aD, o);
    }
    if (lane == 0) { nodeN[w] = aN; nodeD[w] = aD; }
    __syncthreads();

    if (tid < 32) {
        const int n = tid & 15;
        const float* V = (tid < 16) ? nodeN : nodeD;
        float c = 0.f;
#pragma unroll
        for (int k = 0; k < NNODE; k++)
            c += V[k] * cospif((float)(n * (2 * k + 1)) * (1.0f / 32.0f));
        c *= (n == 0) ? (1.0f / NNODE) : (2.0f / NNODE);
        ((tid < 16) ? cN : cD)[n] = c;
    }
    __syncthreads();

    const float u = (a - m) * rcpf_(h);
    const float u2 = u + u;
    float bN1 = 0.f, bN2 = 0.f, bD1 = 0.f, bD2 = 0.f;
#pragma unroll
    for (int n = NNODE - 1; n >= 1; --n) {
        float tN = fmaf(u2, bN1, cN[n] - bN2);
        float tD = fmaf(u2, bD1, cD[n] - bD2);
        bN2 = bN1; bN1 = tN;
        bD2 = bD1; bD1 = tD;
    }
    float fN = fmaf(u, bN1, cN[0] - bN2);
    float fD = fmaf(u, bD1, cD[0] - bD2);
    float v = fN * rcpf_(fD);
    v = v > 0.f ? v : 0.f;

    Mc[idx] = __half_as_ushort(__float2half_rn(v));
}

extern "C" void kernel_launch(void* const* d_in, const int* in_sizes, int n_in,
                              void* d_out, int out_size)
{
    const float* combin = (const float*)d_in[0];
    const float* s_emb  = (const float*)d_in[1];
    const float* W1     = (const float*)d_in[2];
    const float* b1     = (const float*)d_in[3];
    const float* W2     = (const float*)d_in[4];
    const float* b2     = (const float*)d_in[5];
    const float* W3     = (const float*)d_in[6];
    const float* b3     = (const float*)d_in[7];
    float* out = (float*)d_out;

    float *A, *T;
    unsigned short *Xc1, *Xc2, *Wc1, *Wc2, *Wc3, *Mc;
    cudaGetSymbolAddress((void**)&A,   g_A);
    cudaGetSymbolAddress((void**)&T,   g_T);
    cudaGetSymbolAddress((void**)&Xc1, g_Xc1);
    cudaGetSymbolAddress((void**)&Xc2, g_Xc2);
    cudaGetSymbolAddress((void**)&Wc1, g_Wc1);
    cudaGetSymbolAddress((void**)&Wc2, g_Wc2);
    cudaGetSymbolAddress((void**)&Wc3, g_Wc3);
    cudaGetSymbolAddress((void**)&Mc,  g_Mc);
    float* A1p = A + BATCH * HID;
    float* T1p = T + BATCH * HID;

    ConvDesc d0 = { combin, Xc1, BATCH * IN_DIM / 4 };
    ConvDesc d1 = { s_emb,  Xc2, BATCH * HID / 4 };
    ConvDesc d2 = { W2,     Wc1, HID * IN_DIM / 4 };
    ConvDesc d3 = { W1,     Wc2, HID * HID / 4 };
    ConvDesc d4 = { W3,     Wc3, OUT_DIM * HID / 4 };
    convert5<<<dim3(BATCH * IN_DIM / 4 / 256, 5), 256>>>(d0, d1, d2, d3, d4);

    // GEMM1 + GEMM2, each split-K=2: z = prob*2 + sp -> 8 x 16 x 4 = 512 CTAs
    // partials: z0->A[0], z1->A[1], z2->T[0], z3->T[1]; NT = 6,6,4,4
    gemm_mma<<<dim3(HID / 64, BATCH / 64, 4), 256>>>(
        Xc1, Wc1, IN_DIM, Xc2, Wc2, HID,
        A, A1p, T, T1p, HID, 2, /*epi=*/1);

    attn_cheb<<<BATCH, 512>>>(A, A1p, T, T1p, s_emb, b1, b2, Mc, b3, out);

    // GEMM3 split-K=2 (z = chunk): 4 x 16 x 2 = 128 CTAs, NT=4,
    // atomicAdd into out (pre-filled with b3 by attn_cheb)
    gemm_mma<<<dim3(OUT_DIM / 64, BATCH / 64, 2), 256>>>(
        Mc, Wc3, HID, Mc, Wc3, HID,
        out, out, out, out, OUT_DIM, 2, /*epi=*/2);
}